// round 5
// baseline (speedup 1.0000x reference)
#include <cuda_runtime.h>
#include <math.h>

// ---------------------------------------------------------------------------
// VJEPA2 RoPE attention, fp32, sm_103a.
// B=2, S=2048, HID=1024, H=16, D=64, GRID=16, ROT_DIM=20 (per axis).
//
// Pipeline (6 graph-captured launches on the default stream):
//   1-3) q,k,v = hs @ W{q,k,v} + b{q,k,v}          (sgemm_bias)
//   4)   axial RoPE in-place on q and k            (rope_kernel)
//   5)   flash attention -> ctx                     (flash_attn)
//   6)   out = ctx @ Wo + bo                        (sgemm_bias)
//
// All GEMM inner loops use packed fma.rn.f32x2 (2 fp32 FMA / instruction on
// Blackwell) with full fp32 accuracy.
// ---------------------------------------------------------------------------

#define BQ 2
#define SQ 2048
#define HID 1024
#define NH 16
#define HD 64
#define MROWS (BQ * SQ)          // 4096

typedef unsigned long long u64;

// Scratch (static device memory; no allocation APIs used anywhere).
__device__ float g_q[MROWS * HID];
__device__ float g_k[MROWS * HID];
__device__ float g_v[MROWS * HID];
__device__ float g_ctx[MROWS * HID];

// ---- packed f32x2 helpers --------------------------------------------------
__device__ __forceinline__ u64 pack2(float lo, float hi) {
    u64 r;
    asm("mov.b64 %0, {%1, %2};" : "=l"(r) : "f"(lo), "f"(hi));
    return r;
}
__device__ __forceinline__ void unpack2(u64 p, float& lo, float& hi) {
    asm("mov.b64 {%0, %1}, %2;" : "=f"(lo), "=f"(hi) : "l"(p));
}
__device__ __forceinline__ u64 fma2(u64 a, u64 b, u64 c) {
    u64 d;
    asm("fma.rn.f32x2 %0, %1, %2, %3;" : "=l"(d) : "l"(a), "l"(b), "l"(c));
    return d;
}
__device__ __forceinline__ u64 mul2(u64 a, u64 b) {
    u64 d;
    asm("mul.rn.f32x2 %0, %1, %2;" : "=l"(d) : "l"(a), "l"(b));
    return d;
}

// ---------------------------------------------------------------------------
// GEMM: C[M,N] = A[M,K] @ W[K,N] + bias[N]
// BM=64, BN=64, BK=16, 128 threads. Thread tile: 8 rows x 4 cols held as
// 4 row-pair f32x2 accumulators x 4 cols. A staged transposed (As[k][m]) so
// row pairs are contiguous 64-bit loads; W staged row-major (Bs[k][n]).
// ---------------------------------------------------------------------------
__global__ __launch_bounds__(128, 4)
void sgemm_bias(const float* __restrict__ A, const float* __restrict__ W,
                const float* __restrict__ bias, float* __restrict__ C,
                int M, int N, int K)
{
    __shared__ float As[16][64];
    __shared__ float Bs[16][64];

    const int tid = threadIdx.x;
    const int tx = tid & 15;     // col group (4 cols)
    const int ty = tid >> 4;     // row group (8 rows), 0..7
    const int m0 = blockIdx.y * 64;
    const int n0 = blockIdx.x * 64;

    u64 acc[4][4];
#pragma unroll
    for (int i = 0; i < 4; i++)
#pragma unroll
        for (int j = 0; j < 4; j++) acc[i][j] = 0ull;

    const int nK = K >> 4;
    for (int kt = 0; kt < nK; kt++) {
        // stage A (64x16, transposed into As) and W (16x64) — 2 float4 each
#pragma unroll
        for (int i = 0; i < 2; i++) {
            int t = tid + i * 128;
            int mr = t >> 2, kk4 = (t & 3) << 2;
            float4 av = *reinterpret_cast<const float4*>(
                &A[(size_t)(m0 + mr) * K + kt * 16 + kk4]);
            As[kk4 + 0][mr] = av.x;
            As[kk4 + 1][mr] = av.y;
            As[kk4 + 2][mr] = av.z;
            As[kk4 + 3][mr] = av.w;
            int kk = t >> 4, n4 = (t & 15) << 2;
            *reinterpret_cast<float4*>(&Bs[kk][n4]) =
                *reinterpret_cast<const float4*>(
                    &W[(size_t)(kt * 16 + kk) * N + n0 + n4]);
        }
        __syncthreads();

#pragma unroll
        for (int kk = 0; kk < 16; kk++) {
            const u64* ap = reinterpret_cast<const u64*>(&As[kk][8 * ty]);
            u64 a[4];
            a[0] = ap[0]; a[1] = ap[1]; a[2] = ap[2]; a[3] = ap[3];
            float4 bf = *reinterpret_cast<const float4*>(&Bs[kk][4 * tx]);
            u64 b[4];
            b[0] = pack2(bf.x, bf.x);
            b[1] = pack2(bf.y, bf.y);
            b[2] = pack2(bf.z, bf.z);
            b[3] = pack2(bf.w, bf.w);
#pragma unroll
            for (int rp = 0; rp < 4; rp++)
#pragma unroll
                for (int c = 0; c < 4; c++)
                    acc[rp][c] = fma2(a[rp], b[c], acc[rp][c]);
        }
        __syncthreads();
    }

    float4 bv = *reinterpret_cast<const float4*>(&bias[n0 + 4 * tx]);
#pragma unroll
    for (int rp = 0; rp < 4; rp++) {
        float lo[4], hi[4];
#pragma unroll
        for (int c = 0; c < 4; c++) unpack2(acc[rp][c], lo[c], hi[c]);
        int r = m0 + 8 * ty + 2 * rp;
        float4 o0 = make_float4(lo[0] + bv.x, lo[1] + bv.y,
                                lo[2] + bv.z, lo[3] + bv.w);
        float4 o1 = make_float4(hi[0] + bv.x, hi[1] + bv.y,
                                hi[2] + bv.z, hi[3] + bv.w);
        *reinterpret_cast<float4*>(&C[(size_t)r * N + n0 + 4 * tx]) = o0;
        *reinterpret_cast<float4*>(&C[(size_t)(r + 1) * N + n0 + 4 * tx]) = o1;
    }
}

// ---------------------------------------------------------------------------
// Axial RoPE, in-place on q and k. One thread per rotated pair.
// Segment d=[0,20): frame ids; [20,40): height; [40,60): width; [60,64) tail.
// Tiled sin/cos: angle index = (element index within segment) mod 10, so the
// two elements of a pair use DIFFERENT omegas (matches reference exactly).
// ---------------------------------------------------------------------------
__global__ void rope_kernel(float* __restrict__ qb, float* __restrict__ kb)
{
    const int TOT = 2 * MROWS * NH * 30;
    int idx = blockIdx.x * blockDim.x + threadIdx.x;
    if (idx >= TOT) return;

    int p = idx % 30;
    int t = idx / 30;
    int head = t & 15;  t >>= 4;
    int row = t & (MROWS - 1);
    int which = t >> 12;                 // 0 = q, 1 = k
    float* buf = which ? kb : qb;

    int s = row & (SQ - 1);
    int seg = p / 10, w = p - seg * 10;
    int pos;
    if (seg == 0) pos = s >> 8;                       // frame  (256 tok/frame)
    else {
        int rem = s & 255;
        pos = (seg == 1) ? (rem >> 4) : (rem & 15);   // height / width
    }
    int j0 = seg * 20 + 2 * w;
    int i0 = (2 * w) % 10;
    int i1 = (2 * w + 1) % 10;

    float fpos = (float)pos;
    float w0 = powf(10000.0f, -(float)i0 * 0.1f);
    float w1 = powf(10000.0f, -(float)i1 * 0.1f);
    float th0 = fpos * w0, th1 = fpos * w1;

    size_t off = (size_t)row * HID + head * HD + j0;
    float x0 = buf[off], x1 = buf[off + 1];
    buf[off]     = x0 * cosf(th0) - x1 * sinf(th0);
    buf[off + 1] = x1 * cosf(th1) + x0 * sinf(th1);
}

// ---------------------------------------------------------------------------
// Flash attention, exact online softmax, fp32.
// Grid: (S/64 q-tiles, B*H). 256 threads as 16x16: thread (ty,tx) owns
// rows 4ty..4ty+3 and cols 4tx..4tx+3 (cols = keys in GEMM1, d in GEMM2),
// accumulators as f32x2 col-pairs. smem: Qt[d][row], Kt[d][key] (aliased by
// P[row][key] after GEMM1), Vs[key][d] -> exactly 48 KB.
// ---------------------------------------------------------------------------
__global__ __launch_bounds__(256)
void flash_attn(const float* __restrict__ q, const float* __restrict__ k,
                const float* __restrict__ v, float* __restrict__ ctx)
{
    __shared__ float Qt[64][64];    // [d][row], pre-scaled by 1/8
    __shared__ float KtPs[64][64];  // Kt[d][key], reused as P[row][key]
    __shared__ float Vs[64][64];    // [key][d]

    const int tid = threadIdx.x;
    const int tx = tid & 15;
    const int ty = tid >> 4;
    const int bh = blockIdx.y;
    const int b = bh >> 4, h = bh & 15;
    const int q0 = blockIdx.x * 64;
    const size_t base = (size_t)b * SQ * HID + (size_t)h * HD;

    // stage Q tile (transposed, scaled by HEAD_DIM^-0.5 = 0.125)
#pragma unroll
    for (int i = 0; i < 4; i++) {
        int idx = tid + i * 256;
        int row = idx >> 4, d4 = (idx & 15) << 2;
        float4 qv = *reinterpret_cast<const float4*>(
            &q[base + (size_t)(q0 + row) * HID + d4]);
        Qt[d4 + 0][row] = qv.x * 0.125f;
        Qt[d4 + 1][row] = qv.y * 0.125f;
        Qt[d4 + 2][row] = qv.z * 0.125f;
        Qt[d4 + 3][row] = qv.w * 0.125f;
    }

    u64 o[4][2];
    float m_r[4], l_r[4];
#pragma unroll
    for (int j = 0; j < 4; j++) {
        o[j][0] = 0ull; o[j][1] = 0ull;
        m_r[j] = -1e30f; l_r[j] = 0.0f;
    }

    for (int kt = 0; kt < SQ / 64; kt++) {
        __syncthreads();   // previous GEMM2 done reading P/V
        // stage K (transposed) and V tiles
#pragma unroll
        for (int i = 0; i < 4; i++) {
            int idx = tid + i * 256;
            int key = idx >> 4, d4 = (idx & 15) << 2;
            size_t g = base + (size_t)(kt * 64 + key) * HID + d4;
            float4 kv = *reinterpret_cast<const float4*>(&k[g]);
            KtPs[d4 + 0][key] = kv.x;
            KtPs[d4 + 1][key] = kv.y;
            KtPs[d4 + 2][key] = kv.z;
            KtPs[d4 + 3][key] = kv.w;
            *reinterpret_cast<float4*>(&Vs[key][d4]) =
                *reinterpret_cast<const float4*>(&v[g]);
        }
        __syncthreads();

        // GEMM1: S = (Q/8) @ K^T    (inner dim = d)
        u64 s[4][2];
#pragma unroll
        for (int j = 0; j < 4; j++) { s[j][0] = 0ull; s[j][1] = 0ull; }
#pragma unroll 16
        for (int kk = 0; kk < 64; kk++) {
            float4 qf = *reinterpret_cast<const float4*>(&Qt[kk][4 * ty]);
            const u64* bp = reinterpret_cast<const u64*>(&KtPs[kk][4 * tx]);
            u64 b0 = bp[0], b1 = bp[1];
            u64 a0 = pack2(qf.x, qf.x), a1 = pack2(qf.y, qf.y);
            u64 a2 = pack2(qf.z, qf.z), a3 = pack2(qf.w, qf.w);
            s[0][0] = fma2(a0, b0, s[0][0]); s[0][1] = fma2(a0, b1, s[0][1]);
            s[1][0] = fma2(a1, b0, s[1][0]); s[1][1] = fma2(a1, b1, s[1][1]);
            s[2][0] = fma2(a2, b0, s[2][0]); s[2][1] = fma2(a2, b1, s[2][1]);
            s[3][0] = fma2(a3, b0, s[3][0]); s[3][1] = fma2(a3, b1, s[3][1]);
        }
        __syncthreads();   // everyone done reading Kt before P overwrites it

        // online softmax (row reductions across the 16 tx lanes)
        float sc[4][4];
#pragma unroll
        for (int j = 0; j < 4; j++) {
            unpack2(s[j][0], sc[j][0], sc[j][1]);
            unpack2(s[j][1], sc[j][2], sc[j][3]);
        }
#pragma unroll
        for (int j = 0; j < 4; j++) {
            float tm = fmaxf(fmaxf(sc[j][0], sc[j][1]),
                             fmaxf(sc[j][2], sc[j][3]));
#pragma unroll
            for (int off = 1; off < 16; off <<= 1)
                tm = fmaxf(tm, __shfl_xor_sync(0xffffffffu, tm, off));
            float mn = fmaxf(m_r[j], tm);
            float alpha = __expf(m_r[j] - mn);
            m_r[j] = mn;
            float rs = 0.0f;
#pragma unroll
            for (int c = 0; c < 4; c++) {
                sc[j][c] = __expf(sc[j][c] - mn);
                rs += sc[j][c];
            }
#pragma unroll
            for (int off = 1; off < 16; off <<= 1)
                rs += __shfl_xor_sync(0xffffffffu, rs, off);
            l_r[j] = l_r[j] * alpha + rs;
            u64 av = pack2(alpha, alpha);
            o[j][0] = mul2(o[j][0], av);
            o[j][1] = mul2(o[j][1], av);
            // stage P[row][key] (conflict-free: bank = tx-varying)
            KtPs[4 * ty + j][4 * tx + 0] = sc[j][0];
            KtPs[4 * ty + j][4 * tx + 1] = sc[j][1];
            KtPs[4 * ty + j][4 * tx + 2] = sc[j][2];
            KtPs[4 * ty + j][4 * tx + 3] = sc[j][3];
        }
        __syncthreads();

        // GEMM2: O += P @ V    (inner dim = key)
#pragma unroll 16
        for (int kk = 0; kk < 64; kk++) {
            const u64* bp = reinterpret_cast<const u64*>(&Vs[kk][4 * tx]);
            u64 b0 = bp[0], b1 = bp[1];
#pragma unroll
            for (int j = 0; j < 4; j++) {
                float pa = KtPs[4 * ty + j][kk];
                u64 a = pack2(pa, pa);
                o[j][0] = fma2(a, b0, o[j][0]);
                o[j][1] = fma2(a, b1, o[j][1]);
            }
        }
    }

    // epilogue: divide by softmax denominator, write ctx[b,s,h*64+d]
#pragma unroll
    for (int j = 0; j < 4; j++) {
        float inv = 1.0f / l_r[j];
        float x0, x1, x2, x3;
        unpack2(o[j][0], x0, x1);
        unpack2(o[j][1], x2, x3);
        float4 ov = make_float4(x0 * inv, x1 * inv, x2 * inv, x3 * inv);
        *reinterpret_cast<float4*>(
            &ctx[base + (size_t)(q0 + 4 * ty + j) * HID + 4 * tx]) = ov;
    }
}

// ---------------------------------------------------------------------------
extern "C" void kernel_launch(void* const* d_in, const int* in_sizes, int n_in,
                              void* d_out, int out_size)
{
    (void)in_sizes; (void)n_in; (void)out_size;
    const float* hs = (const float*)d_in[0];
    const float* Wq = (const float*)d_in[1];
    const float* bq = (const float*)d_in[2];
    const float* Wk = (const float*)d_in[3];
    const float* bk = (const float*)d_in[4];
    const float* Wv = (const float*)d_in[5];
    const float* bv = (const float*)d_in[6];
    const float* Wo = (const float*)d_in[7];
    const float* bo = (const float*)d_in[8];

    float *qp, *kp, *vp, *cp;
    cudaGetSymbolAddress((void**)&qp, g_q);
    cudaGetSymbolAddress((void**)&kp, g_k);
    cudaGetSymbolAddress((void**)&vp, g_v);
    cudaGetSymbolAddress((void**)&cp, g_ctx);

    dim3 gg(HID / 64, MROWS / 64);   // (16, 64)
    sgemm_bias<<<gg, 128>>>(hs, Wq, bq, qp, MROWS, HID, HID);
    sgemm_bias<<<gg, 128>>>(hs, Wk, bk, kp, MROWS, HID, HID);
    sgemm_bias<<<gg, 128>>>(hs, Wv, bv, vp, MROWS, HID, HID);

    const int TOT = 2 * MROWS * NH * 30;
    rope_kernel<<<(TOT + 255) / 256, 256>>>(qp, kp);

    flash_attn<<<dim3(SQ / 64, BQ * NH), 256>>>(qp, kp, vp, cp);

    sgemm_bias<<<gg, 128>>>(cp, Wo, bo, (float*)d_out, MROWS, HID, HID);
}

// round 10
// speedup vs baseline: 1.2176x; 1.2176x over previous
#include <cuda_runtime.h>
#include <cuda_bf16.h>
#include <math.h>
#include <stdint.h>

// ---------------------------------------------------------------------------
// VJEPA2 RoPE attention, fp32, sm_103a (compiled via compute_103 -> no
// tcgen05; tensor cores reached through legacy mma.sync HMMA path).
//
//   1) hs -> bf16 hi/lo split
//   2) W{q,k,v,o} -> transposed bf16 hi/lo split [N,K]
//   3) fused QKV projection: mma.sync bf16x3 GEMM (M=4096, N=3072)
//   4) axial RoPE in-place on q,k
//   5) flash attention (fp32 packed-FFMA2, exact softmax)
//   6) O projection: same bf16x3 GEMM (N=1024)
// ---------------------------------------------------------------------------

#define BQ 2
#define SQ 2048
#define HID 1024
#define NH 16
#define HD 64
#define MROWS (BQ * SQ)          // 4096

typedef unsigned long long u64;

// ---------------- static scratch (no allocation APIs anywhere) -------------
__device__ __nv_bfloat16 g_ahi[MROWS * HID];
__device__ __nv_bfloat16 g_alo[MROWS * HID];
__device__ __nv_bfloat16 g_wthi[4096 * 1024];   // [N,K]: qkv rows 0..3071, Wo rows 3072..4095
__device__ __nv_bfloat16 g_wtlo[4096 * 1024];
__device__ float g_bias[3072];
__device__ float g_qkv[MROWS * 3072];           // q | k | v  (row stride 3072)
__device__ float g_ctx[MROWS * HID];

// ---------------- packed f32x2 helpers (flash kernel) ----------------------
__device__ __forceinline__ u64 pack2(float lo, float hi) {
    u64 r; asm("mov.b64 %0, {%1, %2};" : "=l"(r) : "f"(lo), "f"(hi)); return r;
}
__device__ __forceinline__ void unpack2(u64 p, float& lo, float& hi) {
    asm("mov.b64 {%0, %1}, %2;" : "=f"(lo), "=f"(hi) : "l"(p));
}
__device__ __forceinline__ u64 fma2(u64 a, u64 b, u64 c) {
    u64 d; asm("fma.rn.f32x2 %0, %1, %2, %3;" : "=l"(d) : "l"(a), "l"(b), "l"(c)); return d;
}
__device__ __forceinline__ u64 mul2(u64 a, u64 b) {
    u64 d; asm("mul.rn.f32x2 %0, %1, %2;" : "=l"(d) : "l"(a), "l"(b)); return d;
}

// ---------------- mma.sync helpers -----------------------------------------
__device__ __forceinline__ uint32_t smem_u32(const void* p) {
    uint32_t a;
    asm("{ .reg .u64 t; cvta.to.shared.u64 t, %1; cvt.u32.u64 %0, t; }" : "=r"(a) : "l"(p));
    return a;
}
__device__ __forceinline__ void ldsm4(uint32_t* r, uint32_t addr) {
    asm volatile("ldmatrix.sync.aligned.m8n8.x4.shared.b16 {%0,%1,%2,%3}, [%4];"
                 : "=r"(r[0]), "=r"(r[1]), "=r"(r[2]), "=r"(r[3]) : "r"(addr));
}
__device__ __forceinline__ void mma16816(float* c, const uint32_t* a,
                                         const uint32_t* b) {
    asm volatile(
        "mma.sync.aligned.m16n8k16.row.col.f32.bf16.bf16.f32 "
        "{%0,%1,%2,%3}, {%4,%5,%6,%7}, {%8,%9}, {%0,%1,%2,%3};"
        : "+f"(c[0]), "+f"(c[1]), "+f"(c[2]), "+f"(c[3])
        : "r"(a[0]), "r"(a[1]), "r"(a[2]), "r"(a[3]), "r"(b[0]), "r"(b[1]));
}

// ---------------------------------------------------------------------------
// Conversion kernels
// ---------------------------------------------------------------------------
__global__ void convert_hilo(const float* __restrict__ x,
                             __nv_bfloat16* __restrict__ hi,
                             __nv_bfloat16* __restrict__ lo, int n4)
{
    int i = blockIdx.x * blockDim.x + threadIdx.x;
    if (i >= n4) return;
    float4 v = reinterpret_cast<const float4*>(x)[i];
    __nv_bfloat16 h0 = __float2bfloat16(v.x), h1 = __float2bfloat16(v.y);
    __nv_bfloat16 h2 = __float2bfloat16(v.z), h3 = __float2bfloat16(v.w);
    __nv_bfloat16 l0 = __float2bfloat16(v.x - __bfloat162float(h0));
    __nv_bfloat16 l1 = __float2bfloat16(v.y - __bfloat162float(h1));
    __nv_bfloat16 l2 = __float2bfloat16(v.z - __bfloat162float(h2));
    __nv_bfloat16 l3 = __float2bfloat16(v.w - __bfloat162float(h3));
    __nv_bfloat162* H = reinterpret_cast<__nv_bfloat162*>(hi);
    __nv_bfloat162* L = reinterpret_cast<__nv_bfloat162*>(lo);
    __nv_bfloat162 p;
    p.x = h0; p.y = h1; H[2 * i] = p;
    p.x = h2; p.y = h3; H[2 * i + 1] = p;
    p.x = l0; p.y = l1; L[2 * i] = p;
    p.x = l2; p.y = l3; L[2 * i + 1] = p;
}

// W [K=1024, N=1024] row-major -> Wt[row_off + n][k] bf16 hi/lo
__global__ void convW(const float* __restrict__ W,
                      __nv_bfloat16* __restrict__ Th,
                      __nv_bfloat16* __restrict__ Tl, int row_off)
{
    __shared__ float t[32][33];
    int n0 = blockIdx.x * 32, k0 = blockIdx.y * 32;
    int tr = threadIdx.x >> 5, tc = threadIdx.x & 31;
#pragma unroll
    for (int i = 0; i < 4; i++)
        t[tr + i * 8][tc] = W[(size_t)(k0 + tr + i * 8) * 1024 + n0 + tc];
    __syncthreads();
#pragma unroll
    for (int i = 0; i < 4; i++) {
        float x = t[tc][tr + i * 8];
        __nv_bfloat16 h = __float2bfloat16(x);
        __nv_bfloat16 l = __float2bfloat16(x - __bfloat162float(h));
        size_t o = (size_t)(row_off + n0 + tr + i * 8) * 1024 + k0 + tc;
        Th[o] = h;
        Tl[o] = l;
    }
}

__global__ void pack_bias(const float* __restrict__ bq, const float* __restrict__ bk,
                          const float* __restrict__ bv, float* __restrict__ out)
{
    int i = blockIdx.x * blockDim.x + threadIdx.x;
    if (i < 1024) out[i] = bq[i];
    else if (i < 2048) out[i] = bk[i - 1024];
    else if (i < 3072) out[i] = bv[i - 2048];
}

// ---------------------------------------------------------------------------
// bf16x3 GEMM via mma.sync: C[128*gy, 128*gx] = A @ B^T + bias
// A hi/lo: [M,1024] row-major bf16.  B hi/lo: [N,1024] row-major bf16.
// 256 threads = 8 warps, warp grid 4(m) x 2(n), warp tile 32x64.
// K chunks of 32. smem rows padded to 80B -> conflict-free ldmatrix.
// Passes per k16: Ahi*Blo, Alo*Bhi, Ahi*Bhi (lo*lo dropped, ~2^-32).
// ---------------------------------------------------------------------------
#define ROWB 80                      // padded smem row stride (bytes)
#define A_LO_OFF 10240               // 128*80
#define B_OFF    20480
#define B_LO_OFF 10240

__global__ void __launch_bounds__(256, 1)
gemm_mma(const __nv_bfloat16* __restrict__ Ah, const __nv_bfloat16* __restrict__ Al,
         const __nv_bfloat16* __restrict__ Bh, const __nv_bfloat16* __restrict__ Bl,
         const float* __restrict__ bias, float* __restrict__ C, int Ntot)
{
    __shared__ __align__(16) char sm[40960];

    const int tid = threadIdx.x;
    const int l = tid & 31;
    const int w = tid >> 5;
    const int wm = w & 3;            // 4 m-warps * 32 rows
    const int wn = w >> 2;           // 2 n-warps * 64 cols
    const int m0 = blockIdx.y * 128;
    const int n0 = blockIdx.x * 128;

    const uint32_t sb = smem_u32(sm);
    const uint32_t sA = sb;
    const uint32_t sB = sb + B_OFF;

    float acc[2][8][4];
#pragma unroll
    for (int mt = 0; mt < 2; mt++)
#pragma unroll
        for (int nj = 0; nj < 8; nj++)
#pragma unroll
            for (int c = 0; c < 4; c++) acc[mt][nj][c] = 0.0f;

    // per-lane ldmatrix address pieces (constant across chunks)
    const int a_row = wm * 32 + (l & 15);
    const int a_kb  = (l & 16);                 // 0 or 16 bytes
    const int b_rbase = wn * 64 + (l & 7) + ((l & 16) >> 1);
    const int b_kb  = ((l & 8) << 1);           // 0 or 16 bytes

    for (int kc = 0; kc < 32; kc++) {
        // ---- stage A/B hi+lo chunk: 128 rows x 32 bf16 each ----
#pragma unroll
        for (int i = 0; i < 2; i++) {
            int e = tid + i * 256;              // 0..511
            int r = e >> 2, q = e & 3;
            size_t ga = (size_t)(m0 + r) * 1024 + kc * 32 + q * 8;
            size_t gb = (size_t)(n0 + r) * 1024 + kc * 32 + q * 8;
            uint32_t so = (uint32_t)(r * ROWB + q * 16);
            *reinterpret_cast<float4*>(sm + so) =
                *reinterpret_cast<const float4*>(Ah + ga);
            *reinterpret_cast<float4*>(sm + A_LO_OFF + so) =
                *reinterpret_cast<const float4*>(Al + ga);
            *reinterpret_cast<float4*>(sm + B_OFF + so) =
                *reinterpret_cast<const float4*>(Bh + gb);
            *reinterpret_cast<float4*>(sm + B_OFF + B_LO_OFF + so) =
                *reinterpret_cast<const float4*>(Bl + gb);
        }
        __syncthreads();

        // ---- compute: two k16 steps ----
#pragma unroll
        for (int ks = 0; ks < 2; ks++) {
            const int kk = ks * 32;             // byte offset of k16 step
            uint32_t ah[2][4], al[2][4], bh[4][4], bl[4][4];
#pragma unroll
            for (int mt = 0; mt < 2; mt++) {
                uint32_t ad = sA + (a_row + mt * 16) * ROWB + kk + a_kb;
                ldsm4(ah[mt], ad);
                ldsm4(al[mt], ad + A_LO_OFF);
            }
#pragma unroll
            for (int np = 0; np < 4; np++) {
                uint32_t bd = sB + (b_rbase + np * 16) * ROWB + kk + b_kb;
                ldsm4(bh[np], bd);
                ldsm4(bl[np], bd + B_LO_OFF);
            }
#pragma unroll
            for (int mt = 0; mt < 2; mt++)
#pragma unroll
                for (int np = 0; np < 4; np++) {
                    mma16816(acc[mt][2 * np],     ah[mt], &bl[np][0]);
                    mma16816(acc[mt][2 * np + 1], ah[mt], &bl[np][2]);
                    mma16816(acc[mt][2 * np],     al[mt], &bh[np][0]);
                    mma16816(acc[mt][2 * np + 1], al[mt], &bh[np][2]);
                    mma16816(acc[mt][2 * np],     ah[mt], &bh[np][0]);
                    mma16816(acc[mt][2 * np + 1], ah[mt], &bh[np][2]);
                }
        }
        __syncthreads();
    }

    // ---- epilogue: bias + store ----
    const int mbase = m0 + wm * 32 + (l >> 2);
    const int nbase = n0 + wn * 64 + 2 * (l & 3);
#pragma unroll
    for (int mt = 0; mt < 2; mt++)
#pragma unroll
        for (int nj = 0; nj < 8; nj++) {
            int mr = mbase + mt * 16;
            int nc = nbase + nj * 8;
            float b0 = bias[nc], b1 = bias[nc + 1];
            float2 v0 = make_float2(acc[mt][nj][0] + b0, acc[mt][nj][1] + b1);
            float2 v1 = make_float2(acc[mt][nj][2] + b0, acc[mt][nj][3] + b1);
            *reinterpret_cast<float2*>(&C[(size_t)mr * Ntot + nc]) = v0;
            *reinterpret_cast<float2*>(&C[(size_t)(mr + 8) * Ntot + nc]) = v1;
        }
}

// ---------------------------------------------------------------------------
// Axial RoPE in-place on q,k inside the fused qkv buffer (row stride 3072).
// ---------------------------------------------------------------------------
__global__ void rope_kernel(float* __restrict__ qkv)
{
    const int TOT = 2 * MROWS * NH * 30;
    int idx = blockIdx.x * blockDim.x + threadIdx.x;
    if (idx >= TOT) return;

    int p = idx % 30;
    int t = idx / 30;
    int head = t & 15;  t >>= 4;
    int row = t & (MROWS - 1);
    int which = t >> 12;                 // 0 = q, 1 = k

    int s = row & (SQ - 1);
    int seg = p / 10, wq = p - seg * 10;
    int pos;
    if (seg == 0) pos = s >> 8;
    else {
        int rem = s & 255;
        pos = (seg == 1) ? (rem >> 4) : (rem & 15);
    }
    int j0 = seg * 20 + 2 * wq;
    int i0 = (2 * wq) % 10;
    int i1 = (2 * wq + 1) % 10;

    float fpos = (float)pos;
    float w0 = powf(10000.0f, -(float)i0 * 0.1f);
    float w1 = powf(10000.0f, -(float)i1 * 0.1f);
    float th0 = fpos * w0, th1 = fpos * w1;

    size_t off = (size_t)row * 3072 + which * 1024 + head * HD + j0;
    float x0 = qkv[off], x1 = qkv[off + 1];
    qkv[off]     = x0 * cosf(th0) - x1 * sinf(th0);
    qkv[off + 1] = x1 * cosf(th1) + x0 * sinf(th1);
}

// ---------------------------------------------------------------------------
// Flash attention (exact online softmax, fp32, packed FFMA2). q/k/v row
// stride = qs (3072 fused); ctx written with stride HID.
// ---------------------------------------------------------------------------
__global__ __launch_bounds__(256)
void flash_attn(const float* __restrict__ q, const float* __restrict__ k,
                const float* __restrict__ v, float* __restrict__ ctx, int qs)
{
    __shared__ float Qt[64][64];
    __shared__ float KtPs[64][64];
    __shared__ float Vs[64][64];

    const int tid = threadIdx.x;
    const int tx = tid & 15;
    const int ty = tid >> 4;
    const int bh = blockIdx.y;
    const int b = bh >> 4, h = bh & 15;
    const int q0 = blockIdx.x * 64;
    const size_t base = (size_t)b * SQ * qs + (size_t)h * HD;
    const size_t cbase = (size_t)b * SQ * HID + (size_t)h * HD;

#pragma unroll
    for (int i = 0; i < 4; i++) {
        int idx = tid + i * 256;
        int row = idx >> 4, d4 = (idx & 15) << 2;
        float4 qv = *reinterpret_cast<const float4*>(
            &q[base + (size_t)(q0 + row) * qs + d4]);
        Qt[d4 + 0][row] = qv.x * 0.125f;
        Qt[d4 + 1][row] = qv.y * 0.125f;
        Qt[d4 + 2][row] = qv.z * 0.125f;
        Qt[d4 + 3][row] = qv.w * 0.125f;
    }

    u64 o[4][2];
    float m_r[4], l_r[4];
#pragma unroll
    for (int j = 0; j < 4; j++) {
        o[j][0] = 0ull; o[j][1] = 0ull;
        m_r[j] = -1e30f; l_r[j] = 0.0f;
    }

    for (int kt = 0; kt < SQ / 64; kt++) {
        __syncthreads();
#pragma unroll
        for (int i = 0; i < 4; i++) {
            int idx = tid + i * 256;
            int key = idx >> 4, d4 = (idx & 15) << 2;
            size_t g = base + (size_t)(kt * 64 + key) * qs + d4;
            float4 kv = *reinterpret_cast<const float4*>(&k[g]);
            KtPs[d4 + 0][key] = kv.x;
            KtPs[d4 + 1][key] = kv.y;
            KtPs[d4 + 2][key] = kv.z;
            KtPs[d4 + 3][key] = kv.w;
            *reinterpret_cast<float4*>(&Vs[key][d4]) =
                *reinterpret_cast<const float4*>(&v[g]);
        }
        __syncthreads();

        u64 s[4][2];
#pragma unroll
        for (int j = 0; j < 4; j++) { s[j][0] = 0ull; s[j][1] = 0ull; }
#pragma unroll 16
        for (int kk = 0; kk < 64; kk++) {
            float4 qf = *reinterpret_cast<const float4*>(&Qt[kk][4 * ty]);
            const u64* bp = reinterpret_cast<const u64*>(&KtPs[kk][4 * tx]);
            u64 b0 = bp[0], b1 = bp[1];
            u64 a0 = pack2(qf.x, qf.x), a1 = pack2(qf.y, qf.y);
            u64 a2 = pack2(qf.z, qf.z), a3 = pack2(qf.w, qf.w);
            s[0][0] = fma2(a0, b0, s[0][0]); s[0][1] = fma2(a0, b1, s[0][1]);
            s[1][0] = fma2(a1, b0, s[1][0]); s[1][1] = fma2(a1, b1, s[1][1]);
            s[2][0] = fma2(a2, b0, s[2][0]); s[2][1] = fma2(a2, b1, s[2][1]);
            s[3][0] = fma2(a3, b0, s[3][0]); s[3][1] = fma2(a3, b1, s[3][1]);
        }
        __syncthreads();

        float sc[4][4];
#pragma unroll
        for (int j = 0; j < 4; j++) {
            unpack2(s[j][0], sc[j][0], sc[j][1]);
            unpack2(s[j][1], sc[j][2], sc[j][3]);
        }
#pragma unroll
        for (int j = 0; j < 4; j++) {
            float tm = fmaxf(fmaxf(sc[j][0], sc[j][1]),
                             fmaxf(sc[j][2], sc[j][3]));
#pragma unroll
            for (int off = 1; off < 16; off <<= 1)
                tm = fmaxf(tm, __shfl_xor_sync(0xffffffffu, tm, off));
            float mn = fmaxf(m_r[j], tm);
            float alpha = __expf(m_r[j] - mn);
            m_r[j] = mn;
            float rs = 0.0f;
#pragma unroll
            for (int c = 0; c < 4; c++) {
                sc[j][c] = __expf(sc[j][c] - mn);
                rs += sc[j][c];
            }
#pragma unroll
            for (int off = 1; off < 16; off <<= 1)
                rs += __shfl_xor_sync(0xffffffffu, rs, off);
            l_r[j] = l_r[j] * alpha + rs;
            u64 av = pack2(alpha, alpha);
            o[j][0] = mul2(o[j][0], av);
            o[j][1] = mul2(o[j][1], av);
            KtPs[4 * ty + j][4 * tx + 0] = sc[j][0];
            KtPs[4 * ty + j][4 * tx + 1] = sc[j][1];
            KtPs[4 * ty + j][4 * tx + 2] = sc[j][2];
            KtPs[4 * ty + j][4 * tx + 3] = sc[j][3];
        }
        __syncthreads();

#pragma unroll 16
        for (int kk = 0; kk < 64; kk++) {
            const u64* bp = reinterpret_cast<const u64*>(&Vs[kk][4 * tx]);
            u64 b0 = bp[0], b1 = bp[1];
#pragma unroll
            for (int j = 0; j < 4; j++) {
                float pa = KtPs[4 * ty + j][kk];
                u64 a = pack2(pa, pa);
                o[j][0] = fma2(a, b0, o[j][0]);
                o[j][1] = fma2(a, b1, o[j][1]);
            }
        }
    }

#pragma unroll
    for (int j = 0; j < 4; j++) {
        float inv = 1.0f / l_r[j];
        float x0, x1, x2, x3;
        unpack2(o[j][0], x0, x1);
        unpack2(o[j][1], x2, x3);
        float4 ov = make_float4(x0 * inv, x1 * inv, x2 * inv, x3 * inv);
        *reinterpret_cast<float4*>(
            &ctx[cbase + (size_t)(q0 + 4 * ty + j) * HID + 4 * tx]) = ov;
    }
}

// ---------------------------------------------------------------------------
extern "C" void kernel_launch(void* const* d_in, const int* in_sizes, int n_in,
                              void* d_out, int out_size)
{
    (void)in_sizes; (void)n_in; (void)out_size;
    const float* hs = (const float*)d_in[0];
    const float* Wq = (const float*)d_in[1];
    const float* bq = (const float*)d_in[2];
    const float* Wk = (const float*)d_in[3];
    const float* bk = (const float*)d_in[4];
    const float* Wv = (const float*)d_in[5];
    const float* bv = (const float*)d_in[6];
    const float* Wo = (const float*)d_in[7];
    const float* bo = (const float*)d_in[8];

    __nv_bfloat16 *ahi, *alo, *wthi, *wtlo;
    float *bias, *qkvp, *cp;
    cudaGetSymbolAddress((void**)&ahi, g_ahi);
    cudaGetSymbolAddress((void**)&alo, g_alo);
    cudaGetSymbolAddress((void**)&wthi, g_wthi);
    cudaGetSymbolAddress((void**)&wtlo, g_wtlo);
    cudaGetSymbolAddress((void**)&bias, g_bias);
    cudaGetSymbolAddress((void**)&qkvp, g_qkv);
    cudaGetSymbolAddress((void**)&cp, g_ctx);

    // conversions
    convert_hilo<<<(MROWS * HID / 4 + 255) / 256, 256>>>(hs, ahi, alo, MROWS * HID / 4);
    dim3 wg(32, 32);
    convW<<<wg, 256>>>(Wq, wthi, wtlo, 0);
    convW<<<wg, 256>>>(Wk, wthi, wtlo, 1024);
    convW<<<wg, 256>>>(Wv, wthi, wtlo, 2048);
    convW<<<wg, 256>>>(Wo, wthi, wtlo, 3072);
    pack_bias<<<12, 256>>>(bq, bk, bv, bias);

    // fused QKV projection: [4096,1024] @ [1024,3072] -> g_qkv
    gemm_mma<<<dim3(24, 32), 256>>>(ahi, alo, wthi, wtlo, bias, qkvp, 3072);

    const int TOT = 2 * MROWS * NH * 30;
    rope_kernel<<<(TOT + 255) / 256, 256>>>(qkvp);

    flash_attn<<<dim3(SQ / 64, BQ * NH), 256>>>(
        qkvp, qkvp + 1024, qkvp + 2048, cp, 3072);

    // O projection
    convert_hilo<<<(MROWS * HID / 4 + 255) / 256, 256>>>(cp, ahi, alo, MROWS * HID / 4);
    gemm_mma<<<dim3(8, 32), 256>>>(
        ahi, alo, wthi + (size_t)3072 * 1024, wtlo + (size_t)3072 * 1024,
        bo, (float*)d_out, 1024);
}

// round 11
// speedup vs baseline: 2.0395x; 1.6750x over previous
#include <cuda_runtime.h>
#include <cuda_bf16.h>
#include <math.h>
#include <stdint.h>

// ---------------------------------------------------------------------------
// VJEPA2 RoPE attention, fp32 I/O, sm_103a via compute_103 (legacy mma.sync
// HMMA path; no tcgen05 on this toolchain).
//
//   1) hs -> bf16 hi/lo split
//   2) W{q,k,v,o} -> transposed bf16 hi/lo [N,K] (Wq,bq pre-scaled by 0.125)
//   3) fused QKV projection GEMM (bf16x3 mma.sync) with RoPE + hi/lo split
//      fused into the epilogue -> qkv hi/lo bf16 buffers
//   4) flash attention fully on mma.sync (bf16x3 both GEMMs, exact fp32
//      online softmax) -> ctx hi/lo bf16
//   5) O projection GEMM -> fp32 d_out
// ---------------------------------------------------------------------------

#define BQ 2
#define SQ 2048
#define HID 1024
#define NH 16
#define HD 64
#define MROWS (BQ * SQ)          // 4096

typedef unsigned long long u64;

// ---------------- static scratch -------------------------------------------
__device__ __nv_bfloat16 g_ahi[MROWS * HID];     // hs split / ctx split (hi)
__device__ __nv_bfloat16 g_alo[MROWS * HID];     // hs split / ctx split (lo)
__device__ __nv_bfloat16 g_wthi[4096 * 1024];    // [N,K]: qkv rows 0..3071, Wo 3072..4095
__device__ __nv_bfloat16 g_wtlo[4096 * 1024];
__device__ float g_bias[3072];
__device__ __nv_bfloat16 g_qkvh[MROWS * 3072];   // q|k|v hi (row stride 3072)
__device__ __nv_bfloat16 g_qkvl[MROWS * 3072];   // q|k|v lo

// ---------------- mma.sync helpers -----------------------------------------
__device__ __forceinline__ uint32_t smem_u32(const void* p) {
    uint32_t a;
    asm("{ .reg .u64 t; cvta.to.shared.u64 t, %1; cvt.u32.u64 %0, t; }" : "=r"(a) : "l"(p));
    return a;
}
__device__ __forceinline__ void ldsm4(uint32_t* r, uint32_t addr) {
    asm volatile("ldmatrix.sync.aligned.m8n8.x4.shared.b16 {%0,%1,%2,%3}, [%4];"
                 : "=r"(r[0]), "=r"(r[1]), "=r"(r[2]), "=r"(r[3]) : "r"(addr));
}
__device__ __forceinline__ void ldsm4t(uint32_t* r, uint32_t addr) {
    asm volatile("ldmatrix.sync.aligned.m8n8.x4.trans.shared.b16 {%0,%1,%2,%3}, [%4];"
                 : "=r"(r[0]), "=r"(r[1]), "=r"(r[2]), "=r"(r[3]) : "r"(addr));
}
__device__ __forceinline__ void mma16816(float* c, const uint32_t* a,
                                         const uint32_t* b) {
    asm volatile(
        "mma.sync.aligned.m16n8k16.row.col.f32.bf16.bf16.f32 "
        "{%0,%1,%2,%3}, {%4,%5,%6,%7}, {%8,%9}, {%0,%1,%2,%3};"
        : "+f"(c[0]), "+f"(c[1]), "+f"(c[2]), "+f"(c[3])
        : "r"(a[0]), "r"(a[1]), "r"(a[2]), "r"(a[3]), "r"(b[0]), "r"(b[1]));
}

// ---------------------------------------------------------------------------
// Conversion kernels
// ---------------------------------------------------------------------------
__global__ void convert_hilo(const float* __restrict__ x,
                             __nv_bfloat16* __restrict__ hi,
                             __nv_bfloat16* __restrict__ lo, int n4)
{
    int i = blockIdx.x * blockDim.x + threadIdx.x;
    if (i >= n4) return;
    float4 v = reinterpret_cast<const float4*>(x)[i];
    __nv_bfloat16 h0 = __float2bfloat16(v.x), h1 = __float2bfloat16(v.y);
    __nv_bfloat16 h2 = __float2bfloat16(v.z), h3 = __float2bfloat16(v.w);
    __nv_bfloat16 l0 = __float2bfloat16(v.x - __bfloat162float(h0));
    __nv_bfloat16 l1 = __float2bfloat16(v.y - __bfloat162float(h1));
    __nv_bfloat16 l2 = __float2bfloat16(v.z - __bfloat162float(h2));
    __nv_bfloat16 l3 = __float2bfloat16(v.w - __bfloat162float(h3));
    __nv_bfloat162* H = reinterpret_cast<__nv_bfloat162*>(hi);
    __nv_bfloat162* L = reinterpret_cast<__nv_bfloat162*>(lo);
    __nv_bfloat162 p;
    p.x = h0; p.y = h1; H[2 * i] = p;
    p.x = h2; p.y = h3; H[2 * i + 1] = p;
    p.x = l0; p.y = l1; L[2 * i] = p;
    p.x = l2; p.y = l3; L[2 * i + 1] = p;
}

// W [K=1024, N=1024] row-major -> Wt[row_off + n][k] bf16 hi/lo, scaled
__global__ void convW(const float* __restrict__ W,
                      __nv_bfloat16* __restrict__ Th,
                      __nv_bfloat16* __restrict__ Tl, int row_off, float scale)
{
    __shared__ float t[32][33];
    int n0 = blockIdx.x * 32, k0 = blockIdx.y * 32;
    int tr = threadIdx.x >> 5, tc = threadIdx.x & 31;
#pragma unroll
    for (int i = 0; i < 4; i++)
        t[tr + i * 8][tc] = W[(size_t)(k0 + tr + i * 8) * 1024 + n0 + tc];
    __syncthreads();
#pragma unroll
    for (int i = 0; i < 4; i++) {
        float x = t[tc][tr + i * 8] * scale;
        __nv_bfloat16 h = __float2bfloat16(x);
        __nv_bfloat16 l = __float2bfloat16(x - __bfloat162float(h));
        size_t o = (size_t)(row_off + n0 + tr + i * 8) * 1024 + k0 + tc;
        Th[o] = h;
        Tl[o] = l;
    }
}

__global__ void pack_bias(const float* __restrict__ bq, const float* __restrict__ bk,
                          const float* __restrict__ bv, float* __restrict__ out)
{
    int i = blockIdx.x * blockDim.x + threadIdx.x;
    if (i < 1024) out[i] = bq[i] * 0.125f;        // fold HEAD_DIM^-0.5 into q
    else if (i < 2048) out[i] = bk[i - 1024];
    else if (i < 3072) out[i] = bv[i - 2048];
}

// ---------------------------------------------------------------------------
// Axial RoPE on one (even,odd) column pair, applied in the GEMM epilogue.
// nc = fused column (q:0..1023, k:1024..2047); mr = token row.
// ---------------------------------------------------------------------------
__device__ __forceinline__ void rope2(float2& v, int mr, int nc)
{
    if (nc >= 2048) return;                  // v: no rope
    int hc = nc & 63;
    if (hc >= 60) return;                    // un-rotated tail
    int seg = hc / 20;
    int wp = (hc % 20) >> 1;                 // pair index 0..9
    int s = mr & (SQ - 1);
    int pos = (seg == 0) ? (s >> 8) : ((seg == 1) ? ((s >> 4) & 15) : (s & 15));
    int i0 = (2 * wp) % 10, i1 = (2 * wp + 1) % 10;
    float fp = (float)pos;
    float th0 = fp * powf(1e4f, -0.1f * (float)i0);
    float th1 = fp * powf(1e4f, -0.1f * (float)i1);
    float sn0, cs0, sn1, cs1;
    sincosf(th0, &sn0, &cs0);
    sincosf(th1, &sn1, &cs1);
    float r0 = v.x * cs0 - v.y * sn0;
    float r1 = v.y * cs1 + v.x * sn1;
    v.x = r0; v.y = r1;
}

__device__ __forceinline__ __nv_bfloat162 split_hi(float2 v, __nv_bfloat162& lo)
{
    __nv_bfloat16 h0 = __float2bfloat16(v.x), h1 = __float2bfloat16(v.y);
    lo.x = __float2bfloat16(v.x - __bfloat162float(h0));
    lo.y = __float2bfloat16(v.y - __bfloat162float(h1));
    __nv_bfloat162 hi; hi.x = h0; hi.y = h1;
    return hi;
}

// ---------------------------------------------------------------------------
// bf16x3 GEMM via mma.sync: C[128*gy, 128*gx] = A @ B^T + bias
// ROPE=1: epilogue applies axial rope (cols<2048) and writes bf16 hi/lo.
// ROPE=0: epilogue writes fp32.
// ---------------------------------------------------------------------------
#define ROWB 80
#define A_LO_OFF 10240
#define B_OFF    20480
#define B_LO_OFF 10240

template <int ROPE>
__global__ void __launch_bounds__(256, 1)
gemm_mma(const __nv_bfloat16* __restrict__ Ah, const __nv_bfloat16* __restrict__ Al,
         const __nv_bfloat16* __restrict__ Bh, const __nv_bfloat16* __restrict__ Bl,
         const float* __restrict__ bias, float* __restrict__ Cf,
         __nv_bfloat16* __restrict__ Ch, __nv_bfloat16* __restrict__ Cl, int Ntot)
{
    __shared__ __align__(16) char sm[40960];

    const int tid = threadIdx.x;
    const int l = tid & 31;
    const int w = tid >> 5;
    const int wm = w & 3;
    const int wn = w >> 2;
    const int m0 = blockIdx.y * 128;
    const int n0 = blockIdx.x * 128;

    const uint32_t sb = smem_u32(sm);
    const uint32_t sA = sb;
    const uint32_t sB = sb + B_OFF;

    float acc[2][8][4];
#pragma unroll
    for (int mt = 0; mt < 2; mt++)
#pragma unroll
        for (int nj = 0; nj < 8; nj++)
#pragma unroll
            for (int c = 0; c < 4; c++) acc[mt][nj][c] = 0.0f;

    const int a_row = wm * 32 + (l & 15);
    const int a_kb  = (l & 16);
    const int b_rbase = wn * 64 + (l & 7) + ((l & 16) >> 1);
    const int b_kb  = ((l & 8) << 1);

    for (int kc = 0; kc < 32; kc++) {
#pragma unroll
        for (int i = 0; i < 2; i++) {
            int e = tid + i * 256;
            int r = e >> 2, q = e & 3;
            size_t ga = (size_t)(m0 + r) * 1024 + kc * 32 + q * 8;
            size_t gb = (size_t)(n0 + r) * 1024 + kc * 32 + q * 8;
            uint32_t so = (uint32_t)(r * ROWB + q * 16);
            *reinterpret_cast<float4*>(sm + so) =
                *reinterpret_cast<const float4*>(Ah + ga);
            *reinterpret_cast<float4*>(sm + A_LO_OFF + so) =
                *reinterpret_cast<const float4*>(Al + ga);
            *reinterpret_cast<float4*>(sm + B_OFF + so) =
                *reinterpret_cast<const float4*>(Bh + gb);
            *reinterpret_cast<float4*>(sm + B_OFF + B_LO_OFF + so) =
                *reinterpret_cast<const float4*>(Bl + gb);
        }
        __syncthreads();

#pragma unroll
        for (int ks = 0; ks < 2; ks++) {
            const int kk = ks * 32;
            uint32_t ah[2][4], al[2][4], bh[4][4], bl[4][4];
#pragma unroll
            for (int mt = 0; mt < 2; mt++) {
                uint32_t ad = sA + (a_row + mt * 16) * ROWB + kk + a_kb;
                ldsm4(ah[mt], ad);
                ldsm4(al[mt], ad + A_LO_OFF);
            }
#pragma unroll
            for (int np = 0; np < 4; np++) {
                uint32_t bd = sB + (b_rbase + np * 16) * ROWB + kk + b_kb;
                ldsm4(bh[np], bd);
                ldsm4(bl[np], bd + B_LO_OFF);
            }
#pragma unroll
            for (int mt = 0; mt < 2; mt++)
#pragma unroll
                for (int np = 0; np < 4; np++) {
                    mma16816(acc[mt][2 * np],     ah[mt], &bl[np][0]);
                    mma16816(acc[mt][2 * np + 1], ah[mt], &bl[np][2]);
                    mma16816(acc[mt][2 * np],     al[mt], &bh[np][0]);
                    mma16816(acc[mt][2 * np + 1], al[mt], &bh[np][2]);
                    mma16816(acc[mt][2 * np],     ah[mt], &bh[np][0]);
                    mma16816(acc[mt][2 * np + 1], ah[mt], &bh[np][2]);
                }
        }
        __syncthreads();
    }

    const int mbase = m0 + wm * 32 + (l >> 2);
    const int nbase = n0 + wn * 64 + 2 * (l & 3);
#pragma unroll
    for (int mt = 0; mt < 2; mt++)
#pragma unroll
        for (int nj = 0; nj < 8; nj++) {
            int mr = mbase + mt * 16;
            int nc = nbase + nj * 8;
            float b0 = bias[nc], b1 = bias[nc + 1];
            float2 v0 = make_float2(acc[mt][nj][0] + b0, acc[mt][nj][1] + b1);
            float2 v1 = make_float2(acc[mt][nj][2] + b0, acc[mt][nj][3] + b1);
            if (ROPE) {
                rope2(v0, mr, nc);
                rope2(v1, mr + 8, nc);
                __nv_bfloat162 lo0, lo1;
                __nv_bfloat162 hi0 = split_hi(v0, lo0);
                __nv_bfloat162 hi1 = split_hi(v1, lo1);
                *reinterpret_cast<__nv_bfloat162*>(&Ch[(size_t)mr * Ntot + nc]) = hi0;
                *reinterpret_cast<__nv_bfloat162*>(&Cl[(size_t)mr * Ntot + nc]) = lo0;
                *reinterpret_cast<__nv_bfloat162*>(&Ch[(size_t)(mr + 8) * Ntot + nc]) = hi1;
                *reinterpret_cast<__nv_bfloat162*>(&Cl[(size_t)(mr + 8) * Ntot + nc]) = lo1;
            } else {
                *reinterpret_cast<float2*>(&Cf[(size_t)mr * Ntot + nc]) = v0;
                *reinterpret_cast<float2*>(&Cf[(size_t)(mr + 8) * Ntot + nc]) = v1;
            }
        }
}

// ---------------------------------------------------------------------------
// Flash attention on mma.sync, bf16x3, exact fp32 online softmax.
// BM=128 q-rows, BN=64 keys, 8 warps (warp w owns rows 16w..16w+15).
// smem: Khi|Klo|Vhi|Vlo (64x144B each) + Phi|Plo (128x144B each) = 73728 B.
// Q is staged through the P area once, then lives in registers.
// ---------------------------------------------------------------------------
#define FROW 144
#define sKh 0
#define sKl 9216
#define sVh 18432
#define sVl 27648
#define sPh 36864
#define sPl 55296
#define FSMEM 73728

__global__ void __launch_bounds__(256, 1)
flash_mma(const __nv_bfloat16* __restrict__ qkvh,
          const __nv_bfloat16* __restrict__ qkvl,
          __nv_bfloat16* __restrict__ ctxh,
          __nv_bfloat16* __restrict__ ctxl)
{
    extern __shared__ __align__(16) char fsm[];
    const int tid = threadIdx.x, l = tid & 31, w = tid >> 5;
    const int bh = blockIdx.y, b = bh >> 4, h = bh & 15;
    const int q0 = blockIdx.x * 128;
    const uint32_t sb = smem_u32(fsm);

    // ---- stage Q hi/lo via the P area, load Q fragments to registers ----
#pragma unroll
    for (int i = 0; i < 8; i++) {
        int e = tid + i * 256;
        int buf = e >> 10, r = (e >> 3) & 127, c8 = e & 7;
        const __nv_bfloat16* sp = buf ? qkvl : qkvh;
        size_t g = (size_t)(b * SQ + q0 + r) * 3072 + h * 64 + c8 * 8;
        *reinterpret_cast<float4*>(fsm + (buf ? sPl : sPh) + r * FROW + c8 * 16) =
            *reinterpret_cast<const float4*>(sp + g);
    }
    __syncthreads();

    uint32_t qh[4][4], ql[4][4];
    {
        uint32_t aQ = sb + sPh + (w * 16 + (l & 15)) * FROW + (l >> 4) * 16;
#pragma unroll
        for (int ks = 0; ks < 4; ks++) {
            ldsm4(qh[ks], aQ + ks * 32);
            ldsm4(ql[ks], aQ + ks * 32 + (sPl - sPh));
        }
    }

    float o[8][4];
    float mrow[2] = { -1e30f, -1e30f };
    float lsum[2] = { 0.0f, 0.0f };
#pragma unroll
    for (int nj = 0; nj < 8; nj++)
#pragma unroll
        for (int c = 0; c < 4; c++) o[nj][c] = 0.0f;

    for (int kt = 0; kt < SQ / 64; kt++) {
        __syncthreads();   // prior MMA1/MMA2 done reading K/V
        // ---- stage K/V hi/lo ----
#pragma unroll
        for (int i = 0; i < 8; i++) {
            int e = tid + i * 256;
            int buf = e >> 9, r = (e >> 3) & 63, c8 = e & 7;
            const __nv_bfloat16* sp = (buf & 1) ? qkvl : qkvh;
            int coloff = ((buf < 2) ? 1024 : 2048) + h * 64;
            size_t g = (size_t)(b * SQ + kt * 64 + r) * 3072 + coloff + c8 * 8;
            *reinterpret_cast<float4*>(fsm + buf * 9216 + r * FROW + c8 * 16) =
                *reinterpret_cast<const float4*>(sp + g);
        }
        __syncthreads();

        // ---- MMA1: S = Q @ K^T (bf16x3) ----
        float sacc[8][4];
#pragma unroll
        for (int nj = 0; nj < 8; nj++)
#pragma unroll
            for (int c = 0; c < 4; c++) sacc[nj][c] = 0.0f;

        uint32_t aK = sb + sKh + ((l & 7) + ((l & 16) >> 1)) * FROW + ((l & 8) << 1);
#pragma unroll
        for (int ks = 0; ks < 4; ks++)
#pragma unroll
            for (int ng = 0; ng < 4; ng++) {
                uint32_t bkh[4], bkl[4];
                uint32_t ad = aK + ng * (16 * FROW) + ks * 32;
                ldsm4(bkh, ad);
                ldsm4(bkl, ad + (sKl - sKh));
                mma16816(sacc[2 * ng],     qh[ks], &bkl[0]);
                mma16816(sacc[2 * ng + 1], qh[ks], &bkl[2]);
                mma16816(sacc[2 * ng],     ql[ks], &bkh[0]);
                mma16816(sacc[2 * ng + 1], ql[ks], &bkh[2]);
                mma16816(sacc[2 * ng],     qh[ks], &bkh[0]);
                mma16816(sacc[2 * ng + 1], qh[ks], &bkh[2]);
            }

        // ---- online softmax (rows r=l>>2 and r+8 of this warp's band) ----
#pragma unroll
        for (int rr = 0; rr < 2; rr++) {
            float vm = -1e30f;
#pragma unroll
            for (int nj = 0; nj < 8; nj++)
                vm = fmaxf(vm, fmaxf(sacc[nj][2 * rr], sacc[nj][2 * rr + 1]));
            vm = fmaxf(vm, __shfl_xor_sync(0xffffffffu, vm, 1));
            vm = fmaxf(vm, __shfl_xor_sync(0xffffffffu, vm, 2));
            float mn = fmaxf(mrow[rr], vm);
            float alpha = __expf(mrow[rr] - mn);
            mrow[rr] = mn;
            float rs = 0.0f;
#pragma unroll
            for (int nj = 0; nj < 8; nj++) {
                float p0 = __expf(sacc[nj][2 * rr] - mn);
                float p1 = __expf(sacc[nj][2 * rr + 1] - mn);
                sacc[nj][2 * rr] = p0;
                sacc[nj][2 * rr + 1] = p1;
                rs += p0 + p1;
            }
            rs += __shfl_xor_sync(0xffffffffu, rs, 1);
            rs += __shfl_xor_sync(0xffffffffu, rs, 2);
            lsum[rr] = lsum[rr] * alpha + rs;
#pragma unroll
            for (int nj = 0; nj < 8; nj++) {
                o[nj][2 * rr] *= alpha;
                o[nj][2 * rr + 1] *= alpha;
            }
            int prow = w * 16 + (l >> 2) + rr * 8;
#pragma unroll
            for (int nj = 0; nj < 8; nj++) {
                float2 pv = make_float2(sacc[nj][2 * rr], sacc[nj][2 * rr + 1]);
                __nv_bfloat162 plo;
                __nv_bfloat162 phi = split_hi(pv, plo);
                int cb = (nj * 8 + 2 * (l & 3)) * 2;
                *reinterpret_cast<__nv_bfloat162*>(fsm + sPh + prow * FROW + cb) = phi;
                *reinterpret_cast<__nv_bfloat162*>(fsm + sPl + prow * FROW + cb) = plo;
            }
        }
        __syncwarp();   // P rows are warp-private; warp-level visibility suffices

        // ---- MMA2: O += P @ V (bf16x3, V via ldmatrix.trans) ----
        uint32_t aP = sb + sPh + (w * 16 + (l & 15)) * FROW + (l >> 4) * 16;
        uint32_t aV = sb + sVh + (l & 15) * FROW + (l >> 4) * 16;
#pragma unroll
        for (int ks = 0; ks < 4; ks++) {
            uint32_t ph[4], pl[4];
            ldsm4(ph, aP + ks * 32);
            ldsm4(pl, aP + ks * 32 + (sPl - sPh));
#pragma unroll
            for (int ng = 0; ng < 4; ng++) {
                uint32_t bvh[4], bvl[4];
                uint32_t ad = aV + ks * (16 * FROW) + ng * 32;
                ldsm4t(bvh, ad);
                ldsm4t(bvl, ad + (sVl - sVh));
                mma16816(o[2 * ng],     ph, &bvl[0]);
                mma16816(o[2 * ng + 1], ph, &bvl[2]);
                mma16816(o[2 * ng],     pl, &bvh[0]);
                mma16816(o[2 * ng + 1], pl, &bvh[2]);
                mma16816(o[2 * ng],     ph, &bvh[0]);
                mma16816(o[2 * ng + 1], ph, &bvh[2]);
            }
        }
    }

    // ---- epilogue: normalize, split hi/lo, write ctx [M,1024] ----
#pragma unroll
    for (int rr = 0; rr < 2; rr++) {
        float inv = 1.0f / lsum[rr];
        size_t row = (size_t)(b * SQ + q0 + w * 16 + (l >> 2) + rr * 8);
#pragma unroll
        for (int nj = 0; nj < 8; nj++) {
            float2 cv = make_float2(o[nj][2 * rr] * inv, o[nj][2 * rr + 1] * inv);
            int col = h * 64 + nj * 8 + 2 * (l & 3);
            __nv_bfloat162 lo;
            __nv_bfloat162 hi = split_hi(cv, lo);
            *reinterpret_cast<__nv_bfloat162*>(&ctxh[row * HID + col]) = hi;
            *reinterpret_cast<__nv_bfloat162*>(&ctxl[row * HID + col]) = lo;
        }
    }
}

// ---------------------------------------------------------------------------
extern "C" void kernel_launch(void* const* d_in, const int* in_sizes, int n_in,
                              void* d_out, int out_size)
{
    (void)in_sizes; (void)n_in; (void)out_size;
    const float* hs = (const float*)d_in[0];
    const float* Wq = (const float*)d_in[1];
    const float* bq = (const float*)d_in[2];
    const float* Wk = (const float*)d_in[3];
    const float* bk = (const float*)d_in[4];
    const float* Wv = (const float*)d_in[5];
    const float* bv = (const float*)d_in[6];
    const float* Wo = (const float*)d_in[7];
    const float* bo = (const float*)d_in[8];

    __nv_bfloat16 *ahi, *alo, *wthi, *wtlo, *qkvh, *qkvl;
    float* bias;
    cudaGetSymbolAddress((void**)&ahi, g_ahi);
    cudaGetSymbolAddress((void**)&alo, g_alo);
    cudaGetSymbolAddress((void**)&wthi, g_wthi);
    cudaGetSymbolAddress((void**)&wtlo, g_wtlo);
    cudaGetSymbolAddress((void**)&bias, g_bias);
    cudaGetSymbolAddress((void**)&qkvh, g_qkvh);
    cudaGetSymbolAddress((void**)&qkvl, g_qkvl);

    cudaFuncSetAttribute(flash_mma,
                         cudaFuncAttributeMaxDynamicSharedMemorySize, FSMEM);

    // conversions (Wq/bq pre-scaled by HEAD_DIM^-0.5 = 0.125)
    convert_hilo<<<(MROWS * HID / 4 + 255) / 256, 256>>>(hs, ahi, alo, MROWS * HID / 4);
    dim3 wg(32, 32);
    convW<<<wg, 256>>>(Wq, wthi, wtlo, 0, 0.125f);
    convW<<<wg, 256>>>(Wk, wthi, wtlo, 1024, 1.0f);
    convW<<<wg, 256>>>(Wv, wthi, wtlo, 2048, 1.0f);
    convW<<<wg, 256>>>(Wo, wthi, wtlo, 3072, 1.0f);
    pack_bias<<<12, 256>>>(bq, bk, bv, bias);

    // fused QKV projection with rope + hi/lo split in epilogue
    gemm_mma<1><<<dim3(24, 32), 256>>>(
        ahi, alo, wthi, wtlo, bias, nullptr, qkvh, qkvl, 3072);

    // flash attention -> ctx hi/lo (reuses g_ahi/g_alo)
    flash_mma<<<dim3(SQ / 128, BQ * NH), 256, FSMEM>>>(qkvh, qkvl, ahi, alo);

    // O projection -> fp32 output
    gemm_mma<0><<<dim3(8, 32), 256>>>(
        ahi, alo, wthi + (size_t)3072 * 1024, wtlo + (size_t)3072 * 1024,
        bo, (float*)d_out, nullptr, nullptr, 1024);
}

// round 12
// speedup vs baseline: 2.3424x; 1.1485x over previous
#include <cuda_runtime.h>
#include <cuda_bf16.h>
#include <math.h>
#include <stdint.h>

// ---------------------------------------------------------------------------
// VJEPA2 RoPE attention, fp32 I/O, sm_103a via compute_103 (legacy mma.sync
// HMMA path; tcgen05 unavailable on this toolchain).
//
// R11: cp.async 2-stage pipelines in both the projection GEMM and flash
// attention (overlap global->smem staging with tensor-core compute; one
// barrier per chunk instead of two).
// ---------------------------------------------------------------------------

#define BQ 2
#define SQ 2048
#define HID 1024
#define NH 16
#define HD 64
#define MROWS (BQ * SQ)          // 4096

typedef unsigned long long u64;

// ---------------- static scratch -------------------------------------------
__device__ __nv_bfloat16 g_ahi[MROWS * HID];     // hs split / ctx split (hi)
__device__ __nv_bfloat16 g_alo[MROWS * HID];     // hs split / ctx split (lo)
__device__ __nv_bfloat16 g_wthi[4096 * 1024];    // [N,K]: qkv rows 0..3071, Wo 3072..4095
__device__ __nv_bfloat16 g_wtlo[4096 * 1024];
__device__ float g_bias[3072];
__device__ __nv_bfloat16 g_qkvh[MROWS * 3072];   // q|k|v hi (row stride 3072)
__device__ __nv_bfloat16 g_qkvl[MROWS * 3072];   // q|k|v lo

// ---------------- helpers --------------------------------------------------
__device__ __forceinline__ uint32_t smem_u32(const void* p) {
    uint32_t a;
    asm("{ .reg .u64 t; cvta.to.shared.u64 t, %1; cvt.u32.u64 %0, t; }" : "=r"(a) : "l"(p));
    return a;
}
__device__ __forceinline__ void ldsm4(uint32_t* r, uint32_t addr) {
    asm volatile("ldmatrix.sync.aligned.m8n8.x4.shared.b16 {%0,%1,%2,%3}, [%4];"
                 : "=r"(r[0]), "=r"(r[1]), "=r"(r[2]), "=r"(r[3]) : "r"(addr));
}
__device__ __forceinline__ void ldsm4t(uint32_t* r, uint32_t addr) {
    asm volatile("ldmatrix.sync.aligned.m8n8.x4.trans.shared.b16 {%0,%1,%2,%3}, [%4];"
                 : "=r"(r[0]), "=r"(r[1]), "=r"(r[2]), "=r"(r[3]) : "r"(addr));
}
__device__ __forceinline__ void mma16816(float* c, const uint32_t* a,
                                         const uint32_t* b) {
    asm volatile(
        "mma.sync.aligned.m16n8k16.row.col.f32.bf16.bf16.f32 "
        "{%0,%1,%2,%3}, {%4,%5,%6,%7}, {%8,%9}, {%0,%1,%2,%3};"
        : "+f"(c[0]), "+f"(c[1]), "+f"(c[2]), "+f"(c[3])
        : "r"(a[0]), "r"(a[1]), "r"(a[2]), "r"(a[3]), "r"(b[0]), "r"(b[1]));
}
__device__ __forceinline__ void cpasync16(uint32_t dst, const void* src) {
    asm volatile("cp.async.cg.shared.global [%0], [%1], 16;"
                 :: "r"(dst), "l"(src) : "memory");
}
__device__ __forceinline__ void cpcommit() {
    asm volatile("cp.async.commit_group;" ::: "memory");
}
__device__ __forceinline__ void cpwait0() {
    asm volatile("cp.async.wait_group 0;" ::: "memory");
}

// ---------------------------------------------------------------------------
// Conversion kernels
// ---------------------------------------------------------------------------
__global__ void convert_hilo(const float* __restrict__ x,
                             __nv_bfloat16* __restrict__ hi,
                             __nv_bfloat16* __restrict__ lo, int n4)
{
    int i = blockIdx.x * blockDim.x + threadIdx.x;
    if (i >= n4) return;
    float4 v = reinterpret_cast<const float4*>(x)[i];
    __nv_bfloat16 h0 = __float2bfloat16(v.x), h1 = __float2bfloat16(v.y);
    __nv_bfloat16 h2 = __float2bfloat16(v.z), h3 = __float2bfloat16(v.w);
    __nv_bfloat16 l0 = __float2bfloat16(v.x - __bfloat162float(h0));
    __nv_bfloat16 l1 = __float2bfloat16(v.y - __bfloat162float(h1));
    __nv_bfloat16 l2 = __float2bfloat16(v.z - __bfloat162float(h2));
    __nv_bfloat16 l3 = __float2bfloat16(v.w - __bfloat162float(h3));
    __nv_bfloat162* H = reinterpret_cast<__nv_bfloat162*>(hi);
    __nv_bfloat162* L = reinterpret_cast<__nv_bfloat162*>(lo);
    __nv_bfloat162 p;
    p.x = h0; p.y = h1; H[2 * i] = p;
    p.x = h2; p.y = h3; H[2 * i + 1] = p;
    p.x = l0; p.y = l1; L[2 * i] = p;
    p.x = l2; p.y = l3; L[2 * i + 1] = p;
}

// W [K=1024, N=1024] row-major -> Wt[row_off + n][k] bf16 hi/lo, scaled
__global__ void convW(const float* __restrict__ W,
                      __nv_bfloat16* __restrict__ Th,
                      __nv_bfloat16* __restrict__ Tl, int row_off, float scale)
{
    __shared__ float t[32][33];
    int n0 = blockIdx.x * 32, k0 = blockIdx.y * 32;
    int tr = threadIdx.x >> 5, tc = threadIdx.x & 31;
#pragma unroll
    for (int i = 0; i < 4; i++)
        t[tr + i * 8][tc] = W[(size_t)(k0 + tr + i * 8) * 1024 + n0 + tc];
    __syncthreads();
#pragma unroll
    for (int i = 0; i < 4; i++) {
        float x = t[tc][tr + i * 8] * scale;
        __nv_bfloat16 h = __float2bfloat16(x);
        __nv_bfloat16 l = __float2bfloat16(x - __bfloat162float(h));
        size_t o = (size_t)(row_off + n0 + tr + i * 8) * 1024 + k0 + tc;
        Th[o] = h;
        Tl[o] = l;
    }
}

__global__ void pack_bias(const float* __restrict__ bq, const float* __restrict__ bk,
                          const float* __restrict__ bv, float* __restrict__ out)
{
    int i = blockIdx.x * blockDim.x + threadIdx.x;
    if (i < 1024) out[i] = bq[i] * 0.125f;        // fold HEAD_DIM^-0.5 into q
    else if (i < 2048) out[i] = bk[i - 1024];
    else if (i < 3072) out[i] = bv[i - 2048];
}

// ---------------------------------------------------------------------------
// Axial RoPE on one (even,odd) column pair (GEMM epilogue).
// ---------------------------------------------------------------------------
__device__ __forceinline__ void rope2(float2& v, int mr, int nc)
{
    if (nc >= 2048) return;                  // v: no rope
    int hc = nc & 63;
    if (hc >= 60) return;                    // un-rotated tail
    int seg = hc / 20;
    int wp = (hc % 20) >> 1;                 // pair index 0..9
    int s = mr & (SQ - 1);
    int pos = (seg == 0) ? (s >> 8) : ((seg == 1) ? ((s >> 4) & 15) : (s & 15));
    int i0 = (2 * wp) % 10, i1 = (2 * wp + 1) % 10;
    float fp = (float)pos;
    float th0 = fp * powf(1e4f, -0.1f * (float)i0);
    float th1 = fp * powf(1e4f, -0.1f * (float)i1);
    float sn0, cs0, sn1, cs1;
    sincosf(th0, &sn0, &cs0);
    sincosf(th1, &sn1, &cs1);
    float r0 = v.x * cs0 - v.y * sn0;
    float r1 = v.y * cs1 + v.x * sn1;
    v.x = r0; v.y = r1;
}

__device__ __forceinline__ __nv_bfloat162 split_hi(float2 v, __nv_bfloat162& lo)
{
    __nv_bfloat16 h0 = __float2bfloat16(v.x), h1 = __float2bfloat16(v.y);
    lo.x = __float2bfloat16(v.x - __bfloat162float(h0));
    lo.y = __float2bfloat16(v.y - __bfloat162float(h1));
    __nv_bfloat162 hi; hi.x = h0; hi.y = h1;
    return hi;
}

// ---------------------------------------------------------------------------
// bf16x3 GEMM, cp.async double-buffered.
// C[128*gy, 128*gx] = A @ B^T + bias.  Stage = Ahi|Alo|Bhi|Blo (10240 each).
// ---------------------------------------------------------------------------
#define ROWB 80
#define GSTG 40960
#define GSMEM (2 * GSTG)

template <int ROPE>
__device__ __forceinline__ void gemm_stage(char* dst, const __nv_bfloat16* Ah,
    const __nv_bfloat16* Al, const __nv_bfloat16* Bh, const __nv_bfloat16* Bl,
    int m0, int n0, int kc, int tid)
{
    uint32_t db = smem_u32(dst);
#pragma unroll
    for (int i = 0; i < 2; i++) {
        int e = tid + i * 256;
        int r = e >> 2, q = e & 3;
        size_t ga = (size_t)(m0 + r) * 1024 + kc * 32 + q * 8;
        size_t gb = (size_t)(n0 + r) * 1024 + kc * 32 + q * 8;
        uint32_t so = (uint32_t)(r * ROWB + q * 16);
        cpasync16(db + so,         Ah + ga);
        cpasync16(db + 10240 + so, Al + ga);
        cpasync16(db + 20480 + so, Bh + gb);
        cpasync16(db + 30720 + so, Bl + gb);
    }
    cpcommit();
}

template <int ROPE>
__global__ void __launch_bounds__(256, 1)
gemm_mma(const __nv_bfloat16* __restrict__ Ah, const __nv_bfloat16* __restrict__ Al,
         const __nv_bfloat16* __restrict__ Bh, const __nv_bfloat16* __restrict__ Bl,
         const float* __restrict__ bias, float* __restrict__ Cf,
         __nv_bfloat16* __restrict__ Ch, __nv_bfloat16* __restrict__ Cl, int Ntot)
{
    extern __shared__ __align__(16) char sm[];

    const int tid = threadIdx.x;
    const int l = tid & 31;
    const int w = tid >> 5;
    const int wm = w & 3;
    const int wn = w >> 2;
    const int m0 = blockIdx.y * 128;
    const int n0 = blockIdx.x * 128;
    const uint32_t sb = smem_u32(sm);

    float acc[2][8][4];
#pragma unroll
    for (int mt = 0; mt < 2; mt++)
#pragma unroll
        for (int nj = 0; nj < 8; nj++)
#pragma unroll
            for (int c = 0; c < 4; c++) acc[mt][nj][c] = 0.0f;

    const int a_row = wm * 32 + (l & 15);
    const int a_kb  = (l & 16);
    const int b_rbase = wn * 64 + (l & 7) + ((l & 16) >> 1);
    const int b_kb  = ((l & 8) << 1);

    gemm_stage<ROPE>(sm, Ah, Al, Bh, Bl, m0, n0, 0, tid);

    for (int kc = 0; kc < 32; kc++) {
        int buf = kc & 1;
        cpwait0();
        __syncthreads();
        if (kc + 1 < 32)
            gemm_stage<ROPE>(sm + (buf ^ 1) * GSTG, Ah, Al, Bh, Bl,
                             m0, n0, kc + 1, tid);

        const uint32_t sA = sb + buf * GSTG;
        const uint32_t sB = sA + 20480;
#pragma unroll
        for (int ks = 0; ks < 2; ks++) {
            const int kk = ks * 32;
            uint32_t ah[2][4], al[2][4], bh[4][4], bl[4][4];
#pragma unroll
            for (int mt = 0; mt < 2; mt++) {
                uint32_t ad = sA + (a_row + mt * 16) * ROWB + kk + a_kb;
                ldsm4(ah[mt], ad);
                ldsm4(al[mt], ad + 10240);
            }
#pragma unroll
            for (int np = 0; np < 4; np++) {
                uint32_t bd = sB + (b_rbase + np * 16) * ROWB + kk + b_kb;
                ldsm4(bh[np], bd);
                ldsm4(bl[np], bd + 10240);
            }
#pragma unroll
            for (int mt = 0; mt < 2; mt++)
#pragma unroll
                for (int np = 0; np < 4; np++) {
                    mma16816(acc[mt][2 * np],     ah[mt], &bl[np][0]);
                    mma16816(acc[mt][2 * np + 1], ah[mt], &bl[np][2]);
                    mma16816(acc[mt][2 * np],     al[mt], &bh[np][0]);
                    mma16816(acc[mt][2 * np + 1], al[mt], &bh[np][2]);
                    mma16816(acc[mt][2 * np],     ah[mt], &bh[np][0]);
                    mma16816(acc[mt][2 * np + 1], ah[mt], &bh[np][2]);
                }
        }
        __syncthreads();   // all warps done reading buf before it is re-staged
    }

    const int mbase = m0 + wm * 32 + (l >> 2);
    const int nbase = n0 + wn * 64 + 2 * (l & 3);
#pragma unroll
    for (int mt = 0; mt < 2; mt++)
#pragma unroll
        for (int nj = 0; nj < 8; nj++) {
            int mr = mbase + mt * 16;
            int nc = nbase + nj * 8;
            float b0 = bias[nc], b1 = bias[nc + 1];
            float2 v0 = make_float2(acc[mt][nj][0] + b0, acc[mt][nj][1] + b1);
            float2 v1 = make_float2(acc[mt][nj][2] + b0, acc[mt][nj][3] + b1);
            if (ROPE) {
                rope2(v0, mr, nc);
                rope2(v1, mr + 8, nc);
                __nv_bfloat162 lo0, lo1;
                __nv_bfloat162 hi0 = split_hi(v0, lo0);
                __nv_bfloat162 hi1 = split_hi(v1, lo1);
                *reinterpret_cast<__nv_bfloat162*>(&Ch[(size_t)mr * Ntot + nc]) = hi0;
                *reinterpret_cast<__nv_bfloat162*>(&Cl[(size_t)mr * Ntot + nc]) = lo0;
                *reinterpret_cast<__nv_bfloat162*>(&Ch[(size_t)(mr + 8) * Ntot + nc]) = hi1;
                *reinterpret_cast<__nv_bfloat162*>(&Cl[(size_t)(mr + 8) * Ntot + nc]) = lo1;
            } else {
                *reinterpret_cast<float2*>(&Cf[(size_t)mr * Ntot + nc]) = v0;
                *reinterpret_cast<float2*>(&Cf[(size_t)(mr + 8) * Ntot + nc]) = v1;
            }
        }
}

// ---------------------------------------------------------------------------
// Flash attention, mma.sync bf16x3, exact fp32 online softmax,
// cp.async double-buffered K/V.
// smem: KV stage x2 (Kh|Kl|Vh|Vl, 9216 each = 36864/stage) + Ph|Pl (18432 ea)
//       = 110592 bytes.
// ---------------------------------------------------------------------------
#define FROW 144
#define KVSTG 36864
#define sPh 73728
#define sPl 92160
#define FSMEM 110592

__device__ __forceinline__ void kv_stage(char* smbase, int stg,
    const __nv_bfloat16* qkvh, const __nv_bfloat16* qkvl,
    int b, int h, int kt, int tid)
{
    uint32_t db = smem_u32(smbase) + stg * KVSTG;
#pragma unroll
    for (int i = 0; i < 8; i++) {
        int e = tid + i * 256;
        int buf = e >> 9, r = (e >> 3) & 63, c8 = e & 7;
        const __nv_bfloat16* sp = (buf & 1) ? qkvl : qkvh;
        int coloff = ((buf < 2) ? 1024 : 2048) + h * 64;
        size_t g = (size_t)(b * SQ + kt * 64 + r) * 3072 + coloff + c8 * 8;
        cpasync16(db + buf * 9216 + r * FROW + c8 * 16, sp + g);
    }
    cpcommit();
}

__global__ void __launch_bounds__(256, 1)
flash_mma(const __nv_bfloat16* __restrict__ qkvh,
          const __nv_bfloat16* __restrict__ qkvl,
          __nv_bfloat16* __restrict__ ctxh,
          __nv_bfloat16* __restrict__ ctxl)
{
    extern __shared__ __align__(16) char fsm[];
    const int tid = threadIdx.x, l = tid & 31, w = tid >> 5;
    const int bh = blockIdx.y, b = bh >> 4, h = bh & 15;
    const int q0 = blockIdx.x * 128;
    const uint32_t sb = smem_u32(fsm);

    // ---- stage Q hi/lo via the P area, load Q fragments to registers ----
#pragma unroll
    for (int i = 0; i < 8; i++) {
        int e = tid + i * 256;
        int buf = e >> 10, r = (e >> 3) & 127, c8 = e & 7;
        const __nv_bfloat16* sp = buf ? qkvl : qkvh;
        size_t g = (size_t)(b * SQ + q0 + r) * 3072 + h * 64 + c8 * 8;
        *reinterpret_cast<float4*>(fsm + (buf ? sPl : sPh) + r * FROW + c8 * 16) =
            *reinterpret_cast<const float4*>(sp + g);
    }
    __syncthreads();

    uint32_t qh[4][4], ql[4][4];
    {
        uint32_t aQ = sb + sPh + (w * 16 + (l & 15)) * FROW + (l >> 4) * 16;
#pragma unroll
        for (int ks = 0; ks < 4; ks++) {
            ldsm4(qh[ks], aQ + ks * 32);
            ldsm4(ql[ks], aQ + ks * 32 + (sPl - sPh));
        }
    }

    // prefetch first K/V tile
    kv_stage(fsm, 0, qkvh, qkvl, b, h, 0, tid);

    float o[8][4];
    float mrow[2] = { -1e30f, -1e30f };
    float lsum[2] = { 0.0f, 0.0f };
#pragma unroll
    for (int nj = 0; nj < 8; nj++)
#pragma unroll
        for (int c = 0; c < 4; c++) o[nj][c] = 0.0f;

    for (int kt = 0; kt < SQ / 64; kt++) {
        int stg = kt & 1;
        cpwait0();
        __syncthreads();   // K/V(kt) ready; all threads done with buf stg^1
        if (kt + 1 < SQ / 64)
            kv_stage(fsm, stg ^ 1, qkvh, qkvl, b, h, kt + 1, tid);

        const uint32_t sK = sb + stg * KVSTG;
        const uint32_t sV = sK + 18432;

        // ---- MMA1: S = Q @ K^T (bf16x3) ----
        float sacc[8][4];
#pragma unroll
        for (int nj = 0; nj < 8; nj++)
#pragma unroll
            for (int c = 0; c < 4; c++) sacc[nj][c] = 0.0f;

        uint32_t aK = sK + ((l & 7) + ((l & 16) >> 1)) * FROW + ((l & 8) << 1);
#pragma unroll
        for (int ks = 0; ks < 4; ks++)
#pragma unroll
            for (int ng = 0; ng < 4; ng++) {
                uint32_t bkh[4], bkl[4];
                uint32_t ad = aK + ng * (16 * FROW) + ks * 32;
                ldsm4(bkh, ad);
                ldsm4(bkl, ad + 9216);
                mma16816(sacc[2 * ng],     qh[ks], &bkl[0]);
                mma16816(sacc[2 * ng + 1], qh[ks], &bkl[2]);
                mma16816(sacc[2 * ng],     ql[ks], &bkh[0]);
                mma16816(sacc[2 * ng + 1], ql[ks], &bkh[2]);
                mma16816(sacc[2 * ng],     qh[ks], &bkh[0]);
                mma16816(sacc[2 * ng + 1], qh[ks], &bkh[2]);
            }

        // ---- online softmax ----
#pragma unroll
        for (int rr = 0; rr < 2; rr++) {
            float vm = -1e30f;
#pragma unroll
            for (int nj = 0; nj < 8; nj++)
                vm = fmaxf(vm, fmaxf(sacc[nj][2 * rr], sacc[nj][2 * rr + 1]));
            vm = fmaxf(vm, __shfl_xor_sync(0xffffffffu, vm, 1));
            vm = fmaxf(vm, __shfl_xor_sync(0xffffffffu, vm, 2));
            float mn = fmaxf(mrow[rr], vm);
            float alpha = __expf(mrow[rr] - mn);
            mrow[rr] = mn;
            float rs = 0.0f;
#pragma unroll
            for (int nj = 0; nj < 8; nj++) {
                float p0 = __expf(sacc[nj][2 * rr] - mn);
                float p1 = __expf(sacc[nj][2 * rr + 1] - mn);
                sacc[nj][2 * rr] = p0;
                sacc[nj][2 * rr + 1] = p1;
                rs += p0 + p1;
            }
            rs += __shfl_xor_sync(0xffffffffu, rs, 1);
            rs += __shfl_xor_sync(0xffffffffu, rs, 2);
            lsum[rr] = lsum[rr] * alpha + rs;
#pragma unroll
            for (int nj = 0; nj < 8; nj++) {
                o[nj][2 * rr] *= alpha;
                o[nj][2 * rr + 1] *= alpha;
            }
            int prow = w * 16 + (l >> 2) + rr * 8;
#pragma unroll
            for (int nj = 0; nj < 8; nj++) {
                float2 pv = make_float2(sacc[nj][2 * rr], sacc[nj][2 * rr + 1]);
                __nv_bfloat162 plo;
                __nv_bfloat162 phi = split_hi(pv, plo);
                int cb = (nj * 8 + 2 * (l & 3)) * 2;
                *reinterpret_cast<__nv_bfloat162*>(fsm + sPh + prow * FROW + cb) = phi;
                *reinterpret_cast<__nv_bfloat162*>(fsm + sPl + prow * FROW + cb) = plo;
            }
        }
        __syncwarp();   // P rows are warp-private

        // ---- MMA2: O += P @ V (bf16x3, V via ldmatrix.trans) ----
        uint32_t aP = sb + sPh + (w * 16 + (l & 15)) * FROW + (l >> 4) * 16;
        uint32_t aV = sV + (l & 15) * FROW + (l >> 4) * 16;
#pragma unroll
        for (int ks = 0; ks < 4; ks++) {
            uint32_t ph[4], pl[4];
            ldsm4(ph, aP + ks * 32);
            ldsm4(pl, aP + ks * 32 + (sPl - sPh));
#pragma unroll
            for (int ng = 0; ng < 4; ng++) {
                uint32_t bvh[4], bvl[4];
                uint32_t ad = aV + ks * (16 * FROW) + ng * 32;
                ldsm4t(bvh, ad);
                ldsm4t(bvl, ad + 9216);
                mma16816(o[2 * ng],     ph, &bvl[0]);
                mma16816(o[2 * ng + 1], ph, &bvl[2]);
                mma16816(o[2 * ng],     pl, &bvh[0]);
                mma16816(o[2 * ng + 1], pl, &bvh[2]);
                mma16816(o[2 * ng],     ph, &bvh[0]);
                mma16816(o[2 * ng + 1], ph, &bvh[2]);
            }
        }
    }

    // ---- epilogue ----
#pragma unroll
    for (int rr = 0; rr < 2; rr++) {
        float inv = 1.0f / lsum[rr];
        size_t row = (size_t)(b * SQ + q0 + w * 16 + (l >> 2) + rr * 8);
#pragma unroll
        for (int nj = 0; nj < 8; nj++) {
            float2 cv = make_float2(o[nj][2 * rr] * inv, o[nj][2 * rr + 1] * inv);
            int col = h * 64 + nj * 8 + 2 * (l & 3);
            __nv_bfloat162 lo;
            __nv_bfloat162 hi = split_hi(cv, lo);
            *reinterpret_cast<__nv_bfloat162*>(&ctxh[row * HID + col]) = hi;
            *reinterpret_cast<__nv_bfloat162*>(&ctxl[row * HID + col]) = lo;
        }
    }
}

// ---------------------------------------------------------------------------
extern "C" void kernel_launch(void* const* d_in, const int* in_sizes, int n_in,
                              void* d_out, int out_size)
{
    (void)in_sizes; (void)n_in; (void)out_size;
    const float* hs = (const float*)d_in[0];
    const float* Wq = (const float*)d_in[1];
    const float* bq = (const float*)d_in[2];
    const float* Wk = (const float*)d_in[3];
    const float* bk = (const float*)d_in[4];
    const float* Wv = (const float*)d_in[5];
    const float* bv = (const float*)d_in[6];
    const float* Wo = (const float*)d_in[7];
    const float* bo = (const float*)d_in[8];

    __nv_bfloat16 *ahi, *alo, *wthi, *wtlo, *qkvh, *qkvl;
    float* bias;
    cudaGetSymbolAddress((void**)&ahi, g_ahi);
    cudaGetSymbolAddress((void**)&alo, g_alo);
    cudaGetSymbolAddress((void**)&wthi, g_wthi);
    cudaGetSymbolAddress((void**)&wtlo, g_wtlo);
    cudaGetSymbolAddress((void**)&bias, g_bias);
    cudaGetSymbolAddress((void**)&qkvh, g_qkvh);
    cudaGetSymbolAddress((void**)&qkvl, g_qkvl);

    cudaFuncSetAttribute(gemm_mma<1>,
                         cudaFuncAttributeMaxDynamicSharedMemorySize, GSMEM);
    cudaFuncSetAttribute(gemm_mma<0>,
                         cudaFuncAttributeMaxDynamicSharedMemorySize, GSMEM);
    cudaFuncSetAttribute(flash_mma,
                         cudaFuncAttributeMaxDynamicSharedMemorySize, FSMEM);

    // conversions (Wq/bq pre-scaled by HEAD_DIM^-0.5 = 0.125)
    convert_hilo<<<(MROWS * HID / 4 + 255) / 256, 256>>>(hs, ahi, alo, MROWS * HID / 4);
    dim3 wg(32, 32);
    convW<<<wg, 256>>>(Wq, wthi, wtlo, 0, 0.125f);
    convW<<<wg, 256>>>(Wk, wthi, wtlo, 1024, 1.0f);
    convW<<<wg, 256>>>(Wv, wthi, wtlo, 2048, 1.0f);
    convW<<<wg, 256>>>(Wo, wthi, wtlo, 3072, 1.0f);
    pack_bias<<<12, 256>>>(bq, bk, bv, bias);

    // fused QKV projection with rope + hi/lo split in epilogue
    gemm_mma<1><<<dim3(24, 32), 256, GSMEM>>>(
        ahi, alo, wthi, wtlo, bias, nullptr, qkvh, qkvl, 3072);

    // flash attention -> ctx hi/lo (reuses g_ahi/g_alo)
    flash_mma<<<dim3(SQ / 128, BQ * NH), 256, FSMEM>>>(qkvh, qkvl, ahi, alo);

    // O projection -> fp32 output
    gemm_mma<0><<<dim3(8, 32), 256, GSMEM>>>(
        ahi, alo, wthi + (size_t)3072 * 1024, wtlo + (size_t)3072 * 1024,
        bo, (float*)d_out, nullptr, nullptr, 1024);
}

// round 14
// speedup vs baseline: 2.3600x; 1.0075x over previous
#include <cuda_runtime.h>
#include <cuda_bf16.h>
#include <math.h>
#include <stdint.h>

// ---------------------------------------------------------------------------
// VJEPA2 RoPE attention, fp32 I/O, sm_103a via compute_103 (legacy mma.sync
// HMMA path; tcgen05 unavailable on this toolchain).
//
// R12: MMA instruction reorder for ILP — pass-outer / tile-inner emission so
// same-accumulator reuse distance covers HMMA latency (was 2 instrs, now
// 8-16). Accumulation order per accumulator unchanged -> identical numerics.
// Also: 4 convW launches merged into one grid-z launch.
// ---------------------------------------------------------------------------

#define BQ 2
#define SQ 2048
#define HID 1024
#define NH 16
#define HD 64
#define MROWS (BQ * SQ)          // 4096

typedef unsigned long long u64;

// ---------------- static scratch -------------------------------------------
__device__ __nv_bfloat16 g_ahi[MROWS * HID];     // hs split / ctx split (hi)
__device__ __nv_bfloat16 g_alo[MROWS * HID];     // hs split / ctx split (lo)
__device__ __nv_bfloat16 g_wthi[4096 * 1024];    // [N,K]: qkv rows 0..3071, Wo 3072..4095
__device__ __nv_bfloat16 g_wtlo[4096 * 1024];
__device__ float g_bias[3072];
__device__ __nv_bfloat16 g_qkvh[MROWS * 3072];   // q|k|v hi (row stride 3072)
__device__ __nv_bfloat16 g_qkvl[MROWS * 3072];   // q|k|v lo

// ---------------- helpers --------------------------------------------------
__device__ __forceinline__ uint32_t smem_u32(const void* p) {
    uint32_t a;
    asm("{ .reg .u64 t; cvta.to.shared.u64 t, %1; cvt.u32.u64 %0, t; }" : "=r"(a) : "l"(p));
    return a;
}
__device__ __forceinline__ void ldsm4(uint32_t* r, uint32_t addr) {
    asm volatile("ldmatrix.sync.aligned.m8n8.x4.shared.b16 {%0,%1,%2,%3}, [%4];"
                 : "=r"(r[0]), "=r"(r[1]), "=r"(r[2]), "=r"(r[3]) : "r"(addr));
}
__device__ __forceinline__ void ldsm4t(uint32_t* r, uint32_t addr) {
    asm volatile("ldmatrix.sync.aligned.m8n8.x4.trans.shared.b16 {%0,%1,%2,%3}, [%4];"
                 : "=r"(r[0]), "=r"(r[1]), "=r"(r[2]), "=r"(r[3]) : "r"(addr));
}
__device__ __forceinline__ void mma16816(float* c, const uint32_t* a,
                                         const uint32_t* b) {
    asm volatile(
        "mma.sync.aligned.m16n8k16.row.col.f32.bf16.bf16.f32 "
        "{%0,%1,%2,%3}, {%4,%5,%6,%7}, {%8,%9}, {%0,%1,%2,%3};"
        : "+f"(c[0]), "+f"(c[1]), "+f"(c[2]), "+f"(c[3])
        : "r"(a[0]), "r"(a[1]), "r"(a[2]), "r"(a[3]), "r"(b[0]), "r"(b[1]));
}
__device__ __forceinline__ void cpasync16(uint32_t dst, const void* src) {
    asm volatile("cp.async.cg.shared.global [%0], [%1], 16;"
                 :: "r"(dst), "l"(src) : "memory");
}
__device__ __forceinline__ void cpcommit() {
    asm volatile("cp.async.commit_group;" ::: "memory");
}
__device__ __forceinline__ void cpwait0() {
    asm volatile("cp.async.wait_group 0;" ::: "memory");
}

// ---------------------------------------------------------------------------
// Conversion kernels
// ---------------------------------------------------------------------------
__global__ void convert_hilo(const float* __restrict__ x,
                             __nv_bfloat16* __restrict__ hi,
                             __nv_bfloat16* __restrict__ lo, int n4)
{
    int i = blockIdx.x * blockDim.x + threadIdx.x;
    if (i >= n4) return;
    float4 v = reinterpret_cast<const float4*>(x)[i];
    __nv_bfloat16 h0 = __float2bfloat16(v.x), h1 = __float2bfloat16(v.y);
    __nv_bfloat16 h2 = __float2bfloat16(v.z), h3 = __float2bfloat16(v.w);
    __nv_bfloat16 l0 = __float2bfloat16(v.x - __bfloat162float(h0));
    __nv_bfloat16 l1 = __float2bfloat16(v.y - __bfloat162float(h1));
    __nv_bfloat16 l2 = __float2bfloat16(v.z - __bfloat162float(h2));
    __nv_bfloat16 l3 = __float2bfloat16(v.w - __bfloat162float(h3));
    __nv_bfloat162* H = reinterpret_cast<__nv_bfloat162*>(hi);
    __nv_bfloat162* L = reinterpret_cast<__nv_bfloat162*>(lo);
    __nv_bfloat162 p;
    p.x = h0; p.y = h1; H[2 * i] = p;
    p.x = h2; p.y = h3; H[2 * i + 1] = p;
    p.x = l0; p.y = l1; L[2 * i] = p;
    p.x = l2; p.y = l3; L[2 * i + 1] = p;
}

// All 4 weight matrices in one launch: z selects W, row_off = 1024*z,
// scale = 0.125 for z==0 (Wq).
__global__ void convW4(const float* __restrict__ W0, const float* __restrict__ W1,
                       const float* __restrict__ W2, const float* __restrict__ W3,
                       __nv_bfloat16* __restrict__ Th,
                       __nv_bfloat16* __restrict__ Tl)
{
    __shared__ float t[32][33];
    int z = blockIdx.z;
    const float* W = (z == 0) ? W0 : (z == 1) ? W1 : (z == 2) ? W2 : W3;
    float scale = (z == 0) ? 0.125f : 1.0f;
    int row_off = z << 10;
    int n0 = blockIdx.x * 32, k0 = blockIdx.y * 32;
    int tr = threadIdx.x >> 5, tc = threadIdx.x & 31;
#pragma unroll
    for (int i = 0; i < 4; i++)
        t[tr + i * 8][tc] = W[(size_t)(k0 + tr + i * 8) * 1024 + n0 + tc];
    __syncthreads();
#pragma unroll
    for (int i = 0; i < 4; i++) {
        float x = t[tc][tr + i * 8] * scale;
        __nv_bfloat16 h = __float2bfloat16(x);
        __nv_bfloat16 l = __float2bfloat16(x - __bfloat162float(h));
        size_t o = (size_t)(row_off + n0 + tr + i * 8) * 1024 + k0 + tc;
        Th[o] = h;
        Tl[o] = l;
    }
}

__global__ void pack_bias(const float* __restrict__ bq, const float* __restrict__ bk,
                          const float* __restrict__ bv, float* __restrict__ out)
{
    int i = blockIdx.x * blockDim.x + threadIdx.x;
    if (i < 1024) out[i] = bq[i] * 0.125f;        // fold HEAD_DIM^-0.5 into q
    else if (i < 2048) out[i] = bk[i - 1024];
    else if (i < 3072) out[i] = bv[i - 2048];
}

// ---------------------------------------------------------------------------
// Axial RoPE on one (even,odd) column pair (GEMM epilogue).
// ---------------------------------------------------------------------------
__device__ __forceinline__ void rope2(float2& v, int mr, int nc)
{
    if (nc >= 2048) return;                  // v: no rope
    int hc = nc & 63;
    if (hc >= 60) return;                    // un-rotated tail
    int seg = hc / 20;
    int wp = (hc % 20) >> 1;                 // pair index 0..9
    int s = mr & (SQ - 1);
    int pos = (seg == 0) ? (s >> 8) : ((seg == 1) ? ((s >> 4) & 15) : (s & 15));
    int i0 = (2 * wp) % 10, i1 = (2 * wp + 1) % 10;
    float fp = (float)pos;
    float th0 = fp * powf(1e4f, -0.1f * (float)i0);
    float th1 = fp * powf(1e4f, -0.1f * (float)i1);
    float sn0, cs0, sn1, cs1;
    sincosf(th0, &sn0, &cs0);
    sincosf(th1, &sn1, &cs1);
    float r0 = v.x * cs0 - v.y * sn0;
    float r1 = v.y * cs1 + v.x * sn1;
    v.x = r0; v.y = r1;
}

__device__ __forceinline__ __nv_bfloat162 split_hi(float2 v, __nv_bfloat162& lo)
{
    __nv_bfloat16 h0 = __float2bfloat16(v.x), h1 = __float2bfloat16(v.y);
    lo.x = __float2bfloat16(v.x - __bfloat162float(h0));
    lo.y = __float2bfloat16(v.y - __bfloat162float(h1));
    __nv_bfloat162 hi; hi.x = h0; hi.y = h1;
    return hi;
}

// ---------------------------------------------------------------------------
// bf16x3 GEMM, cp.async double-buffered, pass-outer mma ordering.
// C[128*gy, 128*gx] = A @ B^T + bias.  Stage = Ahi|Alo|Bhi|Blo (10240 each).
// ---------------------------------------------------------------------------
#define ROWB 80
#define GSTG 40960
#define GSMEM (2 * GSTG)

__device__ __forceinline__ void gemm_stage(char* dst, const __nv_bfloat16* Ah,
    const __nv_bfloat16* Al, const __nv_bfloat16* Bh, const __nv_bfloat16* Bl,
    int m0, int n0, int kc, int tid)
{
    uint32_t db = smem_u32(dst);
#pragma unroll
    for (int i = 0; i < 2; i++) {
        int e = tid + i * 256;
        int r = e >> 2, q = e & 3;
        size_t ga = (size_t)(m0 + r) * 1024 + kc * 32 + q * 8;
        size_t gb = (size_t)(n0 + r) * 1024 + kc * 32 + q * 8;
        uint32_t so = (uint32_t)(r * ROWB + q * 16);
        cpasync16(db + so,         Ah + ga);
        cpasync16(db + 10240 + so, Al + ga);
        cpasync16(db + 20480 + so, Bh + gb);
        cpasync16(db + 30720 + so, Bl + gb);
    }
    cpcommit();
}

template <int ROPE>
__global__ void __launch_bounds__(256, 1)
gemm_mma(const __nv_bfloat16* __restrict__ Ah, const __nv_bfloat16* __restrict__ Al,
         const __nv_bfloat16* __restrict__ Bh, const __nv_bfloat16* __restrict__ Bl,
         const float* __restrict__ bias, float* __restrict__ Cf,
         __nv_bfloat16* __restrict__ Ch, __nv_bfloat16* __restrict__ Cl, int Ntot)
{
    extern __shared__ __align__(16) char sm[];

    const int tid = threadIdx.x;
    const int l = tid & 31;
    const int w = tid >> 5;
    const int wm = w & 3;
    const int wn = w >> 2;
    const int m0 = blockIdx.y * 128;
    const int n0 = blockIdx.x * 128;
    const uint32_t sb = smem_u32(sm);

    float acc[2][8][4];
#pragma unroll
    for (int mt = 0; mt < 2; mt++)
#pragma unroll
        for (int nj = 0; nj < 8; nj++)
#pragma unroll
            for (int c = 0; c < 4; c++) acc[mt][nj][c] = 0.0f;

    const int a_row = wm * 32 + (l & 15);
    const int a_kb  = (l & 16);
    const int b_rbase = wn * 64 + (l & 7) + ((l & 16) >> 1);
    const int b_kb  = ((l & 8) << 1);

    gemm_stage(sm, Ah, Al, Bh, Bl, m0, n0, 0, tid);

    for (int kc = 0; kc < 32; kc++) {
        int buf = kc & 1;
        cpwait0();
        __syncthreads();
        if (kc + 1 < 32)
            gemm_stage(sm + (buf ^ 1) * GSTG, Ah, Al, Bh, Bl,
                       m0, n0, kc + 1, tid);

        const uint32_t sA = sb + buf * GSTG;
        const uint32_t sB = sA + 20480;
#pragma unroll
        for (int ks = 0; ks < 2; ks++) {
            const int kk = ks * 32;
            uint32_t ah[2][4], al[2][4], bh[4][4], bl[4][4];
#pragma unroll
            for (int mt = 0; mt < 2; mt++) {
                uint32_t ad = sA + (a_row + mt * 16) * ROWB + kk + a_kb;
                ldsm4(ah[mt], ad);
                ldsm4(al[mt], ad + 10240);
            }
#pragma unroll
            for (int np = 0; np < 4; np++) {
                uint32_t bd = sB + (b_rbase + np * 16) * ROWB + kk + b_kb;
                ldsm4(bh[np], bd);
                ldsm4(bl[np], bd + 10240);
            }
            // pass 0: Ah*Bl — 16 distinct accumulators before any reuse
#pragma unroll
            for (int mt = 0; mt < 2; mt++)
#pragma unroll
                for (int np = 0; np < 4; np++) {
                    mma16816(acc[mt][2 * np],     ah[mt], &bl[np][0]);
                    mma16816(acc[mt][2 * np + 1], ah[mt], &bl[np][2]);
                }
            // pass 1: Al*Bh
#pragma unroll
            for (int mt = 0; mt < 2; mt++)
#pragma unroll
                for (int np = 0; np < 4; np++) {
                    mma16816(acc[mt][2 * np],     al[mt], &bh[np][0]);
                    mma16816(acc[mt][2 * np + 1], al[mt], &bh[np][2]);
                }
            // pass 2: Ah*Bh
#pragma unroll
            for (int mt = 0; mt < 2; mt++)
#pragma unroll
                for (int np = 0; np < 4; np++) {
                    mma16816(acc[mt][2 * np],     ah[mt], &bh[np][0]);
                    mma16816(acc[mt][2 * np + 1], ah[mt], &bh[np][2]);
                }
        }
        __syncthreads();   // all warps done reading buf before it is re-staged
    }

    const int mbase = m0 + wm * 32 + (l >> 2);
    const int nbase = n0 + wn * 64 + 2 * (l & 3);
#pragma unroll
    for (int mt = 0; mt < 2; mt++)
#pragma unroll
        for (int nj = 0; nj < 8; nj++) {
            int mr = mbase + mt * 16;
            int nc = nbase + nj * 8;
            float b0 = bias[nc], b1 = bias[nc + 1];
            float2 v0 = make_float2(acc[mt][nj][0] + b0, acc[mt][nj][1] + b1);
            float2 v1 = make_float2(acc[mt][nj][2] + b0, acc[mt][nj][3] + b1);
            if (ROPE) {
                rope2(v0, mr, nc);
                rope2(v1, mr + 8, nc);
                __nv_bfloat162 lo0, lo1;
                __nv_bfloat162 hi0 = split_hi(v0, lo0);
                __nv_bfloat162 hi1 = split_hi(v1, lo1);
                *reinterpret_cast<__nv_bfloat162*>(&Ch[(size_t)mr * Ntot + nc]) = hi0;
                *reinterpret_cast<__nv_bfloat162*>(&Cl[(size_t)mr * Ntot + nc]) = lo0;
                *reinterpret_cast<__nv_bfloat162*>(&Ch[(size_t)(mr + 8) * Ntot + nc]) = hi1;
                *reinterpret_cast<__nv_bfloat162*>(&Cl[(size_t)(mr + 8) * Ntot + nc]) = lo1;
            } else {
                *reinterpret_cast<float2*>(&Cf[(size_t)mr * Ntot + nc]) = v0;
                *reinterpret_cast<float2*>(&Cf[(size_t)(mr + 8) * Ntot + nc]) = v1;
            }
        }
}

// ---------------------------------------------------------------------------
// Flash attention, mma.sync bf16x3, exact fp32 online softmax,
// cp.async double-buffered K/V, pass-outer mma ordering.
// ---------------------------------------------------------------------------
#define FROW 144
#define KVSTG 36864
#define sPh 73728
#define sPl 92160
#define FSMEM 110592

__device__ __forceinline__ void kv_stage(char* smbase, int stg,
    const __nv_bfloat16* qkvh, const __nv_bfloat16* qkvl,
    int b, int h, int kt, int tid)
{
    uint32_t db = smem_u32(smbase) + stg * KVSTG;
#pragma unroll
    for (int i = 0; i < 8; i++) {
        int e = tid + i * 256;
        int buf = e >> 9, r = (e >> 3) & 63, c8 = e & 7;
        const __nv_bfloat16* sp = (buf & 1) ? qkvl : qkvh;
        int coloff = ((buf < 2) ? 1024 : 2048) + h * 64;
        size_t g = (size_t)(b * SQ + kt * 64 + r) * 3072 + coloff + c8 * 8;
        cpasync16(db + buf * 9216 + r * FROW + c8 * 16, sp + g);
    }
    cpcommit();
}

__global__ void __launch_bounds__(256, 1)
flash_mma(const __nv_bfloat16* __restrict__ qkvh,
          const __nv_bfloat16* __restrict__ qkvl,
          __nv_bfloat16* __restrict__ ctxh,
          __nv_bfloat16* __restrict__ ctxl)
{
    extern __shared__ __align__(16) char fsm[];
    const int tid = threadIdx.x, l = tid & 31, w = tid >> 5;
    const int bh = blockIdx.y, b = bh >> 4, h = bh & 15;
    const int q0 = blockIdx.x * 128;
    const uint32_t sb = smem_u32(fsm);

    // ---- stage Q hi/lo via the P area, load Q fragments to registers ----
#pragma unroll
    for (int i = 0; i < 8; i++) {
        int e = tid + i * 256;
        int buf = e >> 10, r = (e >> 3) & 127, c8 = e & 7;
        const __nv_bfloat16* sp = buf ? qkvl : qkvh;
        size_t g = (size_t)(b * SQ + q0 + r) * 3072 + h * 64 + c8 * 8;
        *reinterpret_cast<float4*>(fsm + (buf ? sPl : sPh) + r * FROW + c8 * 16) =
            *reinterpret_cast<const float4*>(sp + g);
    }
    __syncthreads();

    uint32_t qh[4][4], ql[4][4];
    {
        uint32_t aQ = sb + sPh + (w * 16 + (l & 15)) * FROW + (l >> 4) * 16;
#pragma unroll
        for (int ks = 0; ks < 4; ks++) {
            ldsm4(qh[ks], aQ + ks * 32);
            ldsm4(ql[ks], aQ + ks * 32 + (sPl - sPh));
        }
    }

    // prefetch first K/V tile
    kv_stage(fsm, 0, qkvh, qkvl, b, h, 0, tid);

    float o[8][4];
    float mrow[2] = { -1e30f, -1e30f };
    float lsum[2] = { 0.0f, 0.0f };
#pragma unroll
    for (int nj = 0; nj < 8; nj++)
#pragma unroll
        for (int c = 0; c < 4; c++) o[nj][c] = 0.0f;

    for (int kt = 0; kt < SQ / 64; kt++) {
        int stg = kt & 1;
        cpwait0();
        __syncthreads();   // K/V(kt) ready; all threads done with buf stg^1
        if (kt + 1 < SQ / 64)
            kv_stage(fsm, stg ^ 1, qkvh, qkvl, b, h, kt + 1, tid);

        const uint32_t sK = sb + stg * KVSTG;
        const uint32_t sV = sK + 18432;

        // ---- MMA1: S = Q @ K^T (bf16x3), pass-outer over 4 ng groups ----
        float sacc[8][4];
#pragma unroll
        for (int nj = 0; nj < 8; nj++)
#pragma unroll
            for (int c = 0; c < 4; c++) sacc[nj][c] = 0.0f;

        uint32_t aK = sK + ((l & 7) + ((l & 16) >> 1)) * FROW + ((l & 8) << 1);
#pragma unroll
        for (int ks = 0; ks < 4; ks++) {
            uint32_t bkh[4][4], bkl[4][4];
#pragma unroll
            for (int ng = 0; ng < 4; ng++) {
                uint32_t ad = aK + ng * (16 * FROW) + ks * 32;
                ldsm4(bkh[ng], ad);
                ldsm4(bkl[ng], ad + 9216);
            }
            // pass 0: Qh*Kl — 8 distinct accumulators before reuse
#pragma unroll
            for (int ng = 0; ng < 4; ng++) {
                mma16816(sacc[2 * ng],     qh[ks], &bkl[ng][0]);
                mma16816(sacc[2 * ng + 1], qh[ks], &bkl[ng][2]);
            }
            // pass 1: Ql*Kh
#pragma unroll
            for (int ng = 0; ng < 4; ng++) {
                mma16816(sacc[2 * ng],     ql[ks], &bkh[ng][0]);
                mma16816(sacc[2 * ng + 1], ql[ks], &bkh[ng][2]);
            }
            // pass 2: Qh*Kh
#pragma unroll
            for (int ng = 0; ng < 4; ng++) {
                mma16816(sacc[2 * ng],     qh[ks], &bkh[ng][0]);
                mma16816(sacc[2 * ng + 1], qh[ks], &bkh[ng][2]);
            }
        }

        // ---- online softmax ----
#pragma unroll
        for (int rr = 0; rr < 2; rr++) {
            float vm = -1e30f;
#pragma unroll
            for (int nj = 0; nj < 8; nj++)
                vm = fmaxf(vm, fmaxf(sacc[nj][2 * rr], sacc[nj][2 * rr + 1]));
            vm = fmaxf(vm, __shfl_xor_sync(0xffffffffu, vm, 1));
            vm = fmaxf(vm, __shfl_xor_sync(0xffffffffu, vm, 2));
            float mn = fmaxf(mrow[rr], vm);
            float alpha = __expf(mrow[rr] - mn);
            mrow[rr] = mn;
            float rs = 0.0f;
#pragma unroll
            for (int nj = 0; nj < 8; nj++) {
                float p0 = __expf(sacc[nj][2 * rr] - mn);
                float p1 = __expf(sacc[nj][2 * rr + 1] - mn);
                sacc[nj][2 * rr] = p0;
                sacc[nj][2 * rr + 1] = p1;
                rs += p0 + p1;
            }
            rs += __shfl_xor_sync(0xffffffffu, rs, 1);
            rs += __shfl_xor_sync(0xffffffffu, rs, 2);
            lsum[rr] = lsum[rr] * alpha + rs;
#pragma unroll
            for (int nj = 0; nj < 8; nj++) {
                o[nj][2 * rr] *= alpha;
                o[nj][2 * rr + 1] *= alpha;
            }
            int prow = w * 16 + (l >> 2) + rr * 8;
#pragma unroll
            for (int nj = 0; nj < 8; nj++) {
                float2 pv = make_float2(sacc[nj][2 * rr], sacc[nj][2 * rr + 1]);
                __nv_bfloat162 plo;
                __nv_bfloat162 phi = split_hi(pv, plo);
                int cb = (nj * 8 + 2 * (l & 3)) * 2;
                *reinterpret_cast<__nv_bfloat162*>(fsm + sPh + prow * FROW + cb) = phi;
                *reinterpret_cast<__nv_bfloat162*>(fsm + sPl + prow * FROW + cb) = plo;
            }
        }
        __syncwarp();   // P rows are warp-private

        // ---- MMA2: O += P @ V (bf16x3, pass-outer) ----
        uint32_t aP = sb + sPh + (w * 16 + (l & 15)) * FROW + (l >> 4) * 16;
        uint32_t aV = sV + (l & 15) * FROW + (l >> 4) * 16;
#pragma unroll
        for (int ks = 0; ks < 4; ks++) {
            uint32_t ph[4], pl[4];
            ldsm4(ph, aP + ks * 32);
            ldsm4(pl, aP + ks * 32 + (sPl - sPh));
            uint32_t bvh[4][4], bvl[4][4];
#pragma unroll
            for (int ng = 0; ng < 4; ng++) {
                uint32_t ad = aV + ks * (16 * FROW) + ng * 32;
                ldsm4t(bvh[ng], ad);
                ldsm4t(bvl[ng], ad + 9216);
            }
            // pass 0: Ph*Vl
#pragma unroll
            for (int ng = 0; ng < 4; ng++) {
                mma16816(o[2 * ng],     ph, &bvl[ng][0]);
                mma16816(o[2 * ng + 1], ph, &bvl[ng][2]);
            }
            // pass 1: Pl*Vh
#pragma unroll
            for (int ng = 0; ng < 4; ng++) {
                mma16816(o[2 * ng],     pl, &bvh[ng][0]);
                mma16816(o[2 * ng + 1], pl, &bvh[ng][2]);
            }
            // pass 2: Ph*Vh
#pragma unroll
            for (int ng = 0; ng < 4; ng++) {
                mma16816(o[2 * ng],     ph, &bvh[ng][0]);
                mma16816(o[2 * ng + 1], ph, &bvh[ng][2]);
            }
        }
    }

    // ---- epilogue ----
#pragma unroll
    for (int rr = 0; rr < 2; rr++) {
        float inv = 1.0f / lsum[rr];
        size_t row = (size_t)(b * SQ + q0 + w * 16 + (l >> 2) + rr * 8);
#pragma unroll
        for (int nj = 0; nj < 8; nj++) {
            float2 cv = make_float2(o[nj][2 * rr] * inv, o[nj][2 * rr + 1] * inv);
            int col = h * 64 + nj * 8 + 2 * (l & 3);
            __nv_bfloat162 lo;
            __nv_bfloat162 hi = split_hi(cv, lo);
            *reinterpret_cast<__nv_bfloat162*>(&ctxh[row * HID + col]) = hi;
            *reinterpret_cast<__nv_bfloat162*>(&ctxl[row * HID + col]) = lo;
        }
    }
}

// ---------------------------------------------------------------------------
extern "C" void kernel_launch(void* const* d_in, const int* in_sizes, int n_in,
                              void* d_out, int out_size)
{
    (void)in_sizes; (void)n_in; (void)out_size;
    const float* hs = (const float*)d_in[0];
    const float* Wq = (const float*)d_in[1];
    const float* bq = (const float*)d_in[2];
    const float* Wk = (const float*)d_in[3];
    const float* bk = (const float*)d_in[4];
    const float* Wv = (const float*)d_in[5];
    const float* bv = (const float*)d_in[6];
    const float* Wo = (const float*)d_in[7];
    const float* bo = (const float*)d_in[8];

    __nv_bfloat16 *ahi, *alo, *wthi, *wtlo, *qkvh, *qkvl;
    float* bias;
    cudaGetSymbolAddress((void**)&ahi, g_ahi);
    cudaGetSymbolAddress((void**)&alo, g_alo);
    cudaGetSymbolAddress((void**)&wthi, g_wthi);
    cudaGetSymbolAddress((void**)&wtlo, g_wtlo);
    cudaGetSymbolAddress((void**)&bias, g_bias);
    cudaGetSymbolAddress((void**)&qkvh, g_qkvh);
    cudaGetSymbolAddress((void**)&qkvl, g_qkvl);

    cudaFuncSetAttribute(gemm_mma<1>,
                         cudaFuncAttributeMaxDynamicSharedMemorySize, GSMEM);
    cudaFuncSetAttribute(gemm_mma<0>,
                         cudaFuncAttributeMaxDynamicSharedMemorySize, GSMEM);
    cudaFuncSetAttribute(flash_mma,
                         cudaFuncAttributeMaxDynamicSharedMemorySize, FSMEM);

    // conversions (Wq/bq pre-scaled by HEAD_DIM^-0.5 = 0.125)
    convert_hilo<<<(MROWS * HID / 4 + 255) / 256, 256>>>(hs, ahi, alo, MROWS * HID / 4);
    convW4<<<dim3(32, 32, 4), 256>>>(Wq, Wk, Wv, Wo, wthi, wtlo);
    pack_bias<<<12, 256>>>(bq, bk, bv, bias);

    // fused QKV projection with rope + hi/lo split in epilogue
    gemm_mma<1><<<dim3(24, 32), 256, GSMEM>>>(
        ahi, alo, wthi, wtlo, bias, nullptr, qkvh, qkvl, 3072);

    // flash attention -> ctx hi/lo (reuses g_ahi/g_alo)
    flash_mma<<<dim3(SQ / 128, BQ * NH), 256, FSMEM>>>(qkvh, qkvl, ahi, alo);

    // O projection -> fp32 output
    gemm_mma<0><<<dim3(8, 32), 256, GSMEM>>>(
        ahi, alo, wthi + (size_t)3072 * 1024, wtlo + (size_t)3072 * 1024,
        bo, (float*)d_out, nullptr, nullptr, 1024);
}

// round 15
// speedup vs baseline: 2.8297x; 1.1990x over previous
#include <cuda_runtime.h>
#include <cuda_bf16.h>
#include <math.h>
#include <stdint.h>

// ---------------------------------------------------------------------------
// VJEPA2 RoPE attention, fp32 I/O, sm_103a via compute_103 (legacy mma.sync
// HMMA path; tcgen05 unavailable on this toolchain).
//
// R14: occupancy fix — 2 CTAs/SM on both heavy kernels.
//   gemm_mma: 128x64 tile (30KB/stage), __launch_bounds__(256,2).
//   flash_mma: __launch_bounds__(256,2) (110.6KB smem x2 fits 228KB SM),
//              K/V fragment staging reduced to half-pairs to fit 128 regs.
// ---------------------------------------------------------------------------

#define BQ 2
#define SQ 2048
#define HID 1024
#define NH 16
#define HD 64
#define MROWS (BQ * SQ)          // 4096

typedef unsigned long long u64;

// ---------------- static scratch -------------------------------------------
__device__ __nv_bfloat16 g_ahi[MROWS * HID];     // hs split / ctx split (hi)
__device__ __nv_bfloat16 g_alo[MROWS * HID];     // hs split / ctx split (lo)
__device__ __nv_bfloat16 g_wthi[4096 * 1024];    // [N,K]: qkv rows 0..3071, Wo 3072..4095
__device__ __nv_bfloat16 g_wtlo[4096 * 1024];
__device__ float g_bias[3072];
__device__ __nv_bfloat16 g_qkvh[MROWS * 3072];   // q|k|v hi (row stride 3072)
__device__ __nv_bfloat16 g_qkvl[MROWS * 3072];   // q|k|v lo

// ---------------- helpers --------------------------------------------------
__device__ __forceinline__ uint32_t smem_u32(const void* p) {
    uint32_t a;
    asm("{ .reg .u64 t; cvta.to.shared.u64 t, %1; cvt.u32.u64 %0, t; }" : "=r"(a) : "l"(p));
    return a;
}
__device__ __forceinline__ void ldsm4(uint32_t* r, uint32_t addr) {
    asm volatile("ldmatrix.sync.aligned.m8n8.x4.shared.b16 {%0,%1,%2,%3}, [%4];"
                 : "=r"(r[0]), "=r"(r[1]), "=r"(r[2]), "=r"(r[3]) : "r"(addr));
}
__device__ __forceinline__ void ldsm4t(uint32_t* r, uint32_t addr) {
    asm volatile("ldmatrix.sync.aligned.m8n8.x4.trans.shared.b16 {%0,%1,%2,%3}, [%4];"
                 : "=r"(r[0]), "=r"(r[1]), "=r"(r[2]), "=r"(r[3]) : "r"(addr));
}
__device__ __forceinline__ void mma16816(float* c, const uint32_t* a,
                                         const uint32_t* b) {
    asm volatile(
        "mma.sync.aligned.m16n8k16.row.col.f32.bf16.bf16.f32 "
        "{%0,%1,%2,%3}, {%4,%5,%6,%7}, {%8,%9}, {%0,%1,%2,%3};"
        : "+f"(c[0]), "+f"(c[1]), "+f"(c[2]), "+f"(c[3])
        : "r"(a[0]), "r"(a[1]), "r"(a[2]), "r"(a[3]), "r"(b[0]), "r"(b[1]));
}
__device__ __forceinline__ void cpasync16(uint32_t dst, const void* src) {
    asm volatile("cp.async.cg.shared.global [%0], [%1], 16;"
                 :: "r"(dst), "l"(src) : "memory");
}
__device__ __forceinline__ void cpcommit() {
    asm volatile("cp.async.commit_group;" ::: "memory");
}
__device__ __forceinline__ void cpwait0() {
    asm volatile("cp.async.wait_group 0;" ::: "memory");
}

// ---------------------------------------------------------------------------
// Conversion kernels
// ---------------------------------------------------------------------------
__global__ void convert_hilo(const float* __restrict__ x,
                             __nv_bfloat16* __restrict__ hi,
                             __nv_bfloat16* __restrict__ lo, int n4)
{
    int i = blockIdx.x * blockDim.x + threadIdx.x;
    if (i >= n4) return;
    float4 v = reinterpret_cast<const float4*>(x)[i];
    __nv_bfloat16 h0 = __float2bfloat16(v.x), h1 = __float2bfloat16(v.y);
    __nv_bfloat16 h2 = __float2bfloat16(v.z), h3 = __float2bfloat16(v.w);
    __nv_bfloat16 l0 = __float2bfloat16(v.x - __bfloat162float(h0));
    __nv_bfloat16 l1 = __float2bfloat16(v.y - __bfloat162float(h1));
    __nv_bfloat16 l2 = __float2bfloat16(v.z - __bfloat162float(h2));
    __nv_bfloat16 l3 = __float2bfloat16(v.w - __bfloat162float(h3));
    __nv_bfloat162* H = reinterpret_cast<__nv_bfloat162*>(hi);
    __nv_bfloat162* L = reinterpret_cast<__nv_bfloat162*>(lo);
    __nv_bfloat162 p;
    p.x = h0; p.y = h1; H[2 * i] = p;
    p.x = h2; p.y = h3; H[2 * i + 1] = p;
    p.x = l0; p.y = l1; L[2 * i] = p;
    p.x = l2; p.y = l3; L[2 * i + 1] = p;
}

__global__ void convW4(const float* __restrict__ W0, const float* __restrict__ W1,
                       const float* __restrict__ W2, const float* __restrict__ W3,
                       __nv_bfloat16* __restrict__ Th,
                       __nv_bfloat16* __restrict__ Tl)
{
    __shared__ float t[32][33];
    int z = blockIdx.z;
    const float* W = (z == 0) ? W0 : (z == 1) ? W1 : (z == 2) ? W2 : W3;
    float scale = (z == 0) ? 0.125f : 1.0f;
    int row_off = z << 10;
    int n0 = blockIdx.x * 32, k0 = blockIdx.y * 32;
    int tr = threadIdx.x >> 5, tc = threadIdx.x & 31;
#pragma unroll
    for (int i = 0; i < 4; i++)
        t[tr + i * 8][tc] = W[(size_t)(k0 + tr + i * 8) * 1024 + n0 + tc];
    __syncthreads();
#pragma unroll
    for (int i = 0; i < 4; i++) {
        float x = t[tc][tr + i * 8] * scale;
        __nv_bfloat16 h = __float2bfloat16(x);
        __nv_bfloat16 l = __float2bfloat16(x - __bfloat162float(h));
        size_t o = (size_t)(row_off + n0 + tr + i * 8) * 1024 + k0 + tc;
        Th[o] = h;
        Tl[o] = l;
    }
}

__global__ void pack_bias(const float* __restrict__ bq, const float* __restrict__ bk,
                          const float* __restrict__ bv, float* __restrict__ out)
{
    int i = blockIdx.x * blockDim.x + threadIdx.x;
    if (i < 1024) out[i] = bq[i] * 0.125f;        // fold HEAD_DIM^-0.5 into q
    else if (i < 2048) out[i] = bk[i - 1024];
    else if (i < 3072) out[i] = bv[i - 2048];
}

// ---------------------------------------------------------------------------
// Axial RoPE on one (even,odd) column pair (GEMM epilogue).
// ---------------------------------------------------------------------------
__device__ __forceinline__ void rope2(float2& v, int mr, int nc)
{
    if (nc >= 2048) return;                  // v: no rope
    int hc = nc & 63;
    if (hc >= 60) return;                    // un-rotated tail
    int seg = hc / 20;
    int wp = (hc % 20) >> 1;                 // pair index 0..9
    int s = mr & (SQ - 1);
    int pos = (seg == 0) ? (s >> 8) : ((seg == 1) ? ((s >> 4) & 15) : (s & 15));
    int i0 = (2 * wp) % 10, i1 = (2 * wp + 1) % 10;
    float fp = (float)pos;
    float th0 = fp * powf(1e4f, -0.1f * (float)i0);
    float th1 = fp * powf(1e4f, -0.1f * (float)i1);
    float sn0, cs0, sn1, cs1;
    sincosf(th0, &sn0, &cs0);
    sincosf(th1, &sn1, &cs1);
    float r0 = v.x * cs0 - v.y * sn0;
    float r1 = v.y * cs1 + v.x * sn1;
    v.x = r0; v.y = r1;
}

__device__ __forceinline__ __nv_bfloat162 split_hi(float2 v, __nv_bfloat162& lo)
{
    __nv_bfloat16 h0 = __float2bfloat16(v.x), h1 = __float2bfloat16(v.y);
    lo.x = __float2bfloat16(v.x - __bfloat162float(h0));
    lo.y = __float2bfloat16(v.y - __bfloat162float(h1));
    __nv_bfloat162 hi; hi.x = h0; hi.y = h1;
    return hi;
}

// ---------------------------------------------------------------------------
// bf16x3 GEMM, 128x64 tile, 2 CTAs/SM, cp.async double-buffered.
// Stage = Ahi(10240) | Alo(10240) | Bhi(5120) | Blo(5120) = 30720 B.
// 8 warps: 4(m) x 2(n); warp tile 32x32.
// ---------------------------------------------------------------------------
#define ROWB 80
#define GSTG 30720
#define GSMEM (2 * GSTG)

__device__ __forceinline__ void gemm_stage(char* dst, const __nv_bfloat16* Ah,
    const __nv_bfloat16* Al, const __nv_bfloat16* Bh, const __nv_bfloat16* Bl,
    int m0, int n0, int kc, int tid)
{
    uint32_t db = smem_u32(dst);
#pragma unroll
    for (int i = 0; i < 4; i++) {               // A hi+lo: 1024 x 16B
        int e = tid + i * 256;
        int buf = e >> 9, r = (e >> 2) & 127, q = e & 3;
        const __nv_bfloat16* sp = buf ? Al : Ah;
        size_t g = (size_t)(m0 + r) * 1024 + kc * 32 + q * 8;
        cpasync16(db + buf * 10240 + r * ROWB + q * 16, sp + g);
    }
#pragma unroll
    for (int i = 0; i < 2; i++) {               // B hi+lo: 512 x 16B
        int e = tid + i * 256;
        int buf = e >> 8, r = (e >> 2) & 63, q = e & 3;
        const __nv_bfloat16* sp = buf ? Bl : Bh;
        size_t g = (size_t)(n0 + r) * 1024 + kc * 32 + q * 8;
        cpasync16(db + 20480 + buf * 5120 + r * ROWB + q * 16, sp + g);
    }
    cpcommit();
}

template <int ROPE>
__global__ void __launch_bounds__(256, 2)
gemm_mma(const __nv_bfloat16* __restrict__ Ah, const __nv_bfloat16* __restrict__ Al,
         const __nv_bfloat16* __restrict__ Bh, const __nv_bfloat16* __restrict__ Bl,
         const float* __restrict__ bias, float* __restrict__ Cf,
         __nv_bfloat16* __restrict__ Ch, __nv_bfloat16* __restrict__ Cl, int Ntot)
{
    extern __shared__ __align__(16) char sm[];

    const int tid = threadIdx.x;
    const int l = tid & 31;
    const int w = tid >> 5;
    const int wm = w & 3;            // 4 m-warps x 32 rows
    const int wn = w >> 2;           // 2 n-warps x 32 cols
    const int m0 = blockIdx.y * 128;
    const int n0 = blockIdx.x * 64;
    const uint32_t sb = smem_u32(sm);

    float acc[2][4][4];
#pragma unroll
    for (int mt = 0; mt < 2; mt++)
#pragma unroll
        for (int nj = 0; nj < 4; nj++)
#pragma unroll
            for (int c = 0; c < 4; c++) acc[mt][nj][c] = 0.0f;

    const int a_row = wm * 32 + (l & 15);
    const int a_kb  = (l & 16);
    const int b_rbase = wn * 32 + (l & 7) + ((l & 16) >> 1);
    const int b_kb  = ((l & 8) << 1);

    gemm_stage(sm, Ah, Al, Bh, Bl, m0, n0, 0, tid);

    for (int kc = 0; kc < 32; kc++) {
        int buf = kc & 1;
        cpwait0();
        __syncthreads();
        if (kc + 1 < 32)
            gemm_stage(sm + (buf ^ 1) * GSTG, Ah, Al, Bh, Bl,
                       m0, n0, kc + 1, tid);

        const uint32_t sA = sb + buf * GSTG;
        const uint32_t sB = sA + 20480;
#pragma unroll
        for (int ks = 0; ks < 2; ks++) {
            const int kk = ks * 32;
            uint32_t ah[2][4], al[2][4], bh[2][4], bl[2][4];
#pragma unroll
            for (int mt = 0; mt < 2; mt++) {
                uint32_t ad = sA + (a_row + mt * 16) * ROWB + kk + a_kb;
                ldsm4(ah[mt], ad);
                ldsm4(al[mt], ad + 10240);
            }
#pragma unroll
            for (int np = 0; np < 2; np++) {
                uint32_t bd = sB + (b_rbase + np * 16) * ROWB + kk + b_kb;
                ldsm4(bh[np], bd);
                ldsm4(bl[np], bd + 5120);
            }
            // pass 0: Ah*Bl — 8 distinct accumulators before any reuse
#pragma unroll
            for (int mt = 0; mt < 2; mt++)
#pragma unroll
                for (int np = 0; np < 2; np++) {
                    mma16816(acc[mt][2 * np],     ah[mt], &bl[np][0]);
                    mma16816(acc[mt][2 * np + 1], ah[mt], &bl[np][2]);
                }
            // pass 1: Al*Bh
#pragma unroll
            for (int mt = 0; mt < 2; mt++)
#pragma unroll
                for (int np = 0; np < 2; np++) {
                    mma16816(acc[mt][2 * np],     al[mt], &bh[np][0]);
                    mma16816(acc[mt][2 * np + 1], al[mt], &bh[np][2]);
                }
            // pass 2: Ah*Bh
#pragma unroll
            for (int mt = 0; mt < 2; mt++)
#pragma unroll
                for (int np = 0; np < 2; np++) {
                    mma16816(acc[mt][2 * np],     ah[mt], &bh[np][0]);
                    mma16816(acc[mt][2 * np + 1], ah[mt], &bh[np][2]);
                }
        }
        __syncthreads();   // all warps done reading buf before it is re-staged
    }

    const int mbase = m0 + wm * 32 + (l >> 2);
    const int nbase = n0 + wn * 32 + 2 * (l & 3);
#pragma unroll
    for (int mt = 0; mt < 2; mt++)
#pragma unroll
        for (int nj = 0; nj < 4; nj++) {
            int mr = mbase + mt * 16;
            int nc = nbase + nj * 8;
            float b0 = bias[nc], b1 = bias[nc + 1];
            float2 v0 = make_float2(acc[mt][nj][0] + b0, acc[mt][nj][1] + b1);
            float2 v1 = make_float2(acc[mt][nj][2] + b0, acc[mt][nj][3] + b1);
            if (ROPE) {
                rope2(v0, mr, nc);
                rope2(v1, mr + 8, nc);
                __nv_bfloat162 lo0, lo1;
                __nv_bfloat162 hi0 = split_hi(v0, lo0);
                __nv_bfloat162 hi1 = split_hi(v1, lo1);
                *reinterpret_cast<__nv_bfloat162*>(&Ch[(size_t)mr * Ntot + nc]) = hi0;
                *reinterpret_cast<__nv_bfloat162*>(&Cl[(size_t)mr * Ntot + nc]) = lo0;
                *reinterpret_cast<__nv_bfloat162*>(&Ch[(size_t)(mr + 8) * Ntot + nc]) = hi1;
                *reinterpret_cast<__nv_bfloat162*>(&Cl[(size_t)(mr + 8) * Ntot + nc]) = lo1;
            } else {
                *reinterpret_cast<float2*>(&Cf[(size_t)mr * Ntot + nc]) = v0;
                *reinterpret_cast<float2*>(&Cf[(size_t)(mr + 8) * Ntot + nc]) = v1;
            }
        }
}

// ---------------------------------------------------------------------------
// Flash attention, mma.sync bf16x3, exact fp32 online softmax,
// cp.async double-buffered K/V, 2 CTAs/SM (reg-capped at 128).
// ---------------------------------------------------------------------------
#define FROW 144
#define KVSTG 36864
#define sPh 73728
#define sPl 92160
#define FSMEM 110592

__device__ __forceinline__ void kv_stage(char* smbase, int stg,
    const __nv_bfloat16* qkvh, const __nv_bfloat16* qkvl,
    int b, int h, int kt, int tid)
{
    uint32_t db = smem_u32(smbase) + stg * KVSTG;
#pragma unroll
    for (int i = 0; i < 8; i++) {
        int e = tid + i * 256;
        int buf = e >> 9, r = (e >> 3) & 63, c8 = e & 7;
        const __nv_bfloat16* sp = (buf & 1) ? qkvl : qkvh;
        int coloff = ((buf < 2) ? 1024 : 2048) + h * 64;
        size_t g = (size_t)(b * SQ + kt * 64 + r) * 3072 + coloff + c8 * 8;
        cpasync16(db + buf * 9216 + r * FROW + c8 * 16, sp + g);
    }
    cpcommit();
}

__global__ void __launch_bounds__(256, 2)
flash_mma(const __nv_bfloat16* __restrict__ qkvh,
          const __nv_bfloat16* __restrict__ qkvl,
          __nv_bfloat16* __restrict__ ctxh,
          __nv_bfloat16* __restrict__ ctxl)
{
    extern __shared__ __align__(16) char fsm[];
    const int tid = threadIdx.x, l = tid & 31, w = tid >> 5;
    const int bh = blockIdx.y, b = bh >> 4, h = bh & 15;
    const int q0 = blockIdx.x * 128;
    const uint32_t sb = smem_u32(fsm);

    // ---- stage Q hi/lo via the P area, load Q fragments to registers ----
#pragma unroll
    for (int i = 0; i < 8; i++) {
        int e = tid + i * 256;
        int buf = e >> 10, r = (e >> 3) & 127, c8 = e & 7;
        const __nv_bfloat16* sp = buf ? qkvl : qkvh;
        size_t g = (size_t)(b * SQ + q0 + r) * 3072 + h * 64 + c8 * 8;
        *reinterpret_cast<float4*>(fsm + (buf ? sPl : sPh) + r * FROW + c8 * 16) =
            *reinterpret_cast<const float4*>(sp + g);
    }
    __syncthreads();

    uint32_t qh[4][4], ql[4][4];
    {
        uint32_t aQ = sb + sPh + (w * 16 + (l & 15)) * FROW + (l >> 4) * 16;
#pragma unroll
        for (int ks = 0; ks < 4; ks++) {
            ldsm4(qh[ks], aQ + ks * 32);
            ldsm4(ql[ks], aQ + ks * 32 + (sPl - sPh));
        }
    }

    // prefetch first K/V tile
    kv_stage(fsm, 0, qkvh, qkvl, b, h, 0, tid);

    float o[8][4];
    float mrow[2] = { -1e30f, -1e30f };
    float lsum[2] = { 0.0f, 0.0f };
#pragma unroll
    for (int nj = 0; nj < 8; nj++)
#pragma unroll
        for (int c = 0; c < 4; c++) o[nj][c] = 0.0f;

    for (int kt = 0; kt < SQ / 64; kt++) {
        int stg = kt & 1;
        cpwait0();
        __syncthreads();   // K/V(kt) ready; all threads done with buf stg^1
        if (kt + 1 < SQ / 64)
            kv_stage(fsm, stg ^ 1, qkvh, qkvl, b, h, kt + 1, tid);

        const uint32_t sK = sb + stg * KVSTG;
        const uint32_t sV = sK + 18432;

        // ---- MMA1: S = Q @ K^T (bf16x3), half-pair fragment staging ----
        float sacc[8][4];
#pragma unroll
        for (int nj = 0; nj < 8; nj++)
#pragma unroll
            for (int c = 0; c < 4; c++) sacc[nj][c] = 0.0f;

        uint32_t aK = sK + ((l & 7) + ((l & 16) >> 1)) * FROW + ((l & 8) << 1);
#pragma unroll
        for (int ks = 0; ks < 4; ks++)
#pragma unroll
            for (int hf = 0; hf < 2; hf++) {
                uint32_t bkh[2][4], bkl[2][4];
#pragma unroll
                for (int g = 0; g < 2; g++) {
                    uint32_t ad = aK + (2 * hf + g) * (16 * FROW) + ks * 32;
                    ldsm4(bkh[g], ad);
                    ldsm4(bkl[g], ad + 9216);
                }
#pragma unroll
                for (int g = 0; g < 2; g++) {
                    int ng = 2 * hf + g;
                    mma16816(sacc[2 * ng],     qh[ks], &bkl[g][0]);
                    mma16816(sacc[2 * ng + 1], qh[ks], &bkl[g][2]);
                }
#pragma unroll
                for (int g = 0; g < 2; g++) {
                    int ng = 2 * hf + g;
                    mma16816(sacc[2 * ng],     ql[ks], &bkh[g][0]);
                    mma16816(sacc[2 * ng + 1], ql[ks], &bkh[g][2]);
                }
#pragma unroll
                for (int g = 0; g < 2; g++) {
                    int ng = 2 * hf + g;
                    mma16816(sacc[2 * ng],     qh[ks], &bkh[g][0]);
                    mma16816(sacc[2 * ng + 1], qh[ks], &bkh[g][2]);
                }
            }

        // ---- online softmax ----
#pragma unroll
        for (int rr = 0; rr < 2; rr++) {
            float vm = -1e30f;
#pragma unroll
            for (int nj = 0; nj < 8; nj++)
                vm = fmaxf(vm, fmaxf(sacc[nj][2 * rr], sacc[nj][2 * rr + 1]));
            vm = fmaxf(vm, __shfl_xor_sync(0xffffffffu, vm, 1));
            vm = fmaxf(vm, __shfl_xor_sync(0xffffffffu, vm, 2));
            float mn = fmaxf(mrow[rr], vm);
            float alpha = __expf(mrow[rr] - mn);
            mrow[rr] = mn;
            float rs = 0.0f;
#pragma unroll
            for (int nj = 0; nj < 8; nj++) {
                float p0 = __expf(sacc[nj][2 * rr] - mn);
                float p1 = __expf(sacc[nj][2 * rr + 1] - mn);
                sacc[nj][2 * rr] = p0;
                sacc[nj][2 * rr + 1] = p1;
                rs += p0 + p1;
            }
            rs += __shfl_xor_sync(0xffffffffu, rs, 1);
            rs += __shfl_xor_sync(0xffffffffu, rs, 2);
            lsum[rr] = lsum[rr] * alpha + rs;
#pragma unroll
            for (int nj = 0; nj < 8; nj++) {
                o[nj][2 * rr] *= alpha;
                o[nj][2 * rr + 1] *= alpha;
            }
            int prow = w * 16 + (l >> 2) + rr * 8;
#pragma unroll
            for (int nj = 0; nj < 8; nj++) {
                float2 pv = make_float2(sacc[nj][2 * rr], sacc[nj][2 * rr + 1]);
                __nv_bfloat162 plo;
                __nv_bfloat162 phi = split_hi(pv, plo);
                int cb = (nj * 8 + 2 * (l & 3)) * 2;
                *reinterpret_cast<__nv_bfloat162*>(fsm + sPh + prow * FROW + cb) = phi;
                *reinterpret_cast<__nv_bfloat162*>(fsm + sPl + prow * FROW + cb) = plo;
            }
        }
        __syncwarp();   // P rows are warp-private

        // ---- MMA2: O += P @ V (bf16x3, half-pair staging) ----
        uint32_t aP = sb + sPh + (w * 16 + (l & 15)) * FROW + (l >> 4) * 16;
        uint32_t aV = sV + (l & 15) * FROW + (l >> 4) * 16;
#pragma unroll
        for (int ks = 0; ks < 4; ks++) {
            uint32_t ph[4], pl[4];
            ldsm4(ph, aP + ks * 32);
            ldsm4(pl, aP + ks * 32 + (sPl - sPh));
#pragma unroll
            for (int hf = 0; hf < 2; hf++) {
                uint32_t bvh[2][4], bvl[2][4];
#pragma unroll
                for (int g = 0; g < 2; g++) {
                    uint32_t ad = aV + ks * (16 * FROW) + (2 * hf + g) * 32;
                    ldsm4t(bvh[g], ad);
                    ldsm4t(bvl[g], ad + 9216);
                }
#pragma unroll
                for (int g = 0; g < 2; g++) {
                    int ng = 2 * hf + g;
                    mma16816(o[2 * ng],     ph, &bvl[g][0]);
                    mma16816(o[2 * ng + 1], ph, &bvl[g][2]);
                }
#pragma unroll
                for (int g = 0; g < 2; g++) {
                    int ng = 2 * hf + g;
                    mma16816(o[2 * ng],     pl, &bvh[g][0]);
                    mma16816(o[2 * ng + 1], pl, &bvh[g][2]);
                }
#pragma unroll
                for (int g = 0; g < 2; g++) {
                    int ng = 2 * hf + g;
                    mma16816(o[2 * ng],     ph, &bvh[g][0]);
                    mma16816(o[2 * ng + 1], ph, &bvh[g][2]);
                }
            }
        }
    }

    // ---- epilogue ----
#pragma unroll
    for (int rr = 0; rr < 2; rr++) {
        float inv = 1.0f / lsum[rr];
        size_t row = (size_t)(b * SQ + q0 + w * 16 + (l >> 2) + rr * 8);
#pragma unroll
        for (int nj = 0; nj < 8; nj++) {
            float2 cv = make_float2(o[nj][2 * rr] * inv, o[nj][2 * rr + 1] * inv);
            int col = h * 64 + nj * 8 + 2 * (l & 3);
            __nv_bfloat162 lo;
            __nv_bfloat162 hi = split_hi(cv, lo);
            *reinterpret_cast<__nv_bfloat162*>(&ctxh[row * HID + col]) = hi;
            *reinterpret_cast<__nv_bfloat162*>(&ctxl[row * HID + col]) = lo;
        }
    }
}

// ---------------------------------------------------------------------------
extern "C" void kernel_launch(void* const* d_in, const int* in_sizes, int n_in,
                              void* d_out, int out_size)
{
    (void)in_sizes; (void)n_in; (void)out_size;
    const float* hs = (const float*)d_in[0];
    const float* Wq = (const float*)d_in[1];
    const float* bq = (const float*)d_in[2];
    const float* Wk = (const float*)d_in[3];
    const float* bk = (const float*)d_in[4];
    const float* Wv = (const float*)d_in[5];
    const float* bv = (const float*)d_in[6];
    const float* Wo = (const float*)d_in[7];
    const float* bo = (const float*)d_in[8];

    __nv_bfloat16 *ahi, *alo, *wthi, *wtlo, *qkvh, *qkvl;
    float* bias;
    cudaGetSymbolAddress((void**)&ahi, g_ahi);
    cudaGetSymbolAddress((void**)&alo, g_alo);
    cudaGetSymbolAddress((void**)&wthi, g_wthi);
    cudaGetSymbolAddress((void**)&wtlo, g_wtlo);
    cudaGetSymbolAddress((void**)&bias, g_bias);
    cudaGetSymbolAddress((void**)&qkvh, g_qkvh);
    cudaGetSymbolAddress((void**)&qkvl, g_qkvl);

    cudaFuncSetAttribute(gemm_mma<1>,
                         cudaFuncAttributeMaxDynamicSharedMemorySize, GSMEM);
    cudaFuncSetAttribute(gemm_mma<0>,
                         cudaFuncAttributeMaxDynamicSharedMemorySize, GSMEM);
    cudaFuncSetAttribute(flash_mma,
                         cudaFuncAttributeMaxDynamicSharedMemorySize, FSMEM);

    // conversions (Wq/bq pre-scaled by HEAD_DIM^-0.5 = 0.125)
    convert_hilo<<<(MROWS * HID / 4 + 255) / 256, 256>>>(hs, ahi, alo, MROWS * HID / 4);
    convW4<<<dim3(32, 32, 4), 256>>>(Wq, Wk, Wv, Wo, wthi, wtlo);
    pack_bias<<<12, 256>>>(bq, bk, bv, bias);

    // fused QKV projection with rope + hi/lo split in epilogue
    gemm_mma<1><<<dim3(48, 32), 256, GSMEM>>>(
        ahi, alo, wthi, wtlo, bias, nullptr, qkvh, qkvl, 3072);

    // flash attention -> ctx hi/lo (reuses g_ahi/g_alo)
    flash_mma<<<dim3(SQ / 128, BQ * NH), 256, FSMEM>>>(qkvh, qkvl, ahi, alo);

    // O projection -> fp32 output
    gemm_mma<0><<<dim3(16, 32), 256, GSMEM>>>(
        ahi, alo, wthi + (size_t)3072 * 1024, wtlo + (size_t)3072 * 1024,
        bo, (float*)d_out, nullptr, nullptr, 1024);
}

// round 17
// speedup vs baseline: 2.8432x; 1.0048x over previous
#include <cuda_runtime.h>
#include <cuda_bf16.h>
#include <math.h>
#include <stdint.h>

// ---------------------------------------------------------------------------
// VJEPA2 RoPE attention, fp32 I/O, sm_103a via compute_103 (legacy mma.sync
// HMMA path; tcgen05 unavailable on this toolchain).
//
// R15: gemm_mma back to 128x128 tile while KEEPING 2 CTAs/SM
// (80KB smem/CTA, reg budget ~115 via half-pair B fragment staging).
// flash_mma unchanged from R14 (2 CTAs/SM).
// ---------------------------------------------------------------------------

#define BQ 2
#define SQ 2048
#define HID 1024
#define NH 16
#define HD 64
#define MROWS (BQ * SQ)          // 4096

typedef unsigned long long u64;

// ---------------- static scratch -------------------------------------------
__device__ __nv_bfloat16 g_ahi[MROWS * HID];     // hs split / ctx split (hi)
__device__ __nv_bfloat16 g_alo[MROWS * HID];     // hs split / ctx split (lo)
__device__ __nv_bfloat16 g_wthi[4096 * 1024];    // [N,K]: qkv rows 0..3071, Wo 3072..4095
__device__ __nv_bfloat16 g_wtlo[4096 * 1024];
__device__ float g_bias[3072];
__device__ __nv_bfloat16 g_qkvh[MROWS * 3072];   // q|k|v hi (row stride 3072)
__device__ __nv_bfloat16 g_qkvl[MROWS * 3072];   // q|k|v lo

// ---------------- helpers --------------------------------------------------
__device__ __forceinline__ uint32_t smem_u32(const void* p) {
    uint32_t a;
    asm("{ .reg .u64 t; cvta.to.shared.u64 t, %1; cvt.u32.u64 %0, t; }" : "=r"(a) : "l"(p));
    return a;
}
__device__ __forceinline__ void ldsm4(uint32_t* r, uint32_t addr) {
    asm volatile("ldmatrix.sync.aligned.m8n8.x4.shared.b16 {%0,%1,%2,%3}, [%4];"
                 : "=r"(r[0]), "=r"(r[1]), "=r"(r[2]), "=r"(r[3]) : "r"(addr));
}
__device__ __forceinline__ void ldsm4t(uint32_t* r, uint32_t addr) {
    asm volatile("ldmatrix.sync.aligned.m8n8.x4.trans.shared.b16 {%0,%1,%2,%3}, [%4];"
                 : "=r"(r[0]), "=r"(r[1]), "=r"(r[2]), "=r"(r[3]) : "r"(addr));
}
__device__ __forceinline__ void mma16816(float* c, const uint32_t* a,
                                         const uint32_t* b) {
    asm volatile(
        "mma.sync.aligned.m16n8k16.row.col.f32.bf16.bf16.f32 "
        "{%0,%1,%2,%3}, {%4,%5,%6,%7}, {%8,%9}, {%0,%1,%2,%3};"
        : "+f"(c[0]), "+f"(c[1]), "+f"(c[2]), "+f"(c[3])
        : "r"(a[0]), "r"(a[1]), "r"(a[2]), "r"(a[3]), "r"(b[0]), "r"(b[1]));
}
__device__ __forceinline__ void cpasync16(uint32_t dst, const void* src) {
    asm volatile("cp.async.cg.shared.global [%0], [%1], 16;"
                 :: "r"(dst), "l"(src) : "memory");
}
__device__ __forceinline__ void cpcommit() {
    asm volatile("cp.async.commit_group;" ::: "memory");
}
__device__ __forceinline__ void cpwait0() {
    asm volatile("cp.async.wait_group 0;" ::: "memory");
}

// ---------------------------------------------------------------------------
// Conversion kernels
// ---------------------------------------------------------------------------
__global__ void convert_hilo(const float* __restrict__ x,
                             __nv_bfloat16* __restrict__ hi,
                             __nv_bfloat16* __restrict__ lo, int n4)
{
    int i = blockIdx.x * blockDim.x + threadIdx.x;
    if (i >= n4) return;
    float4 v = reinterpret_cast<const float4*>(x)[i];
    __nv_bfloat16 h0 = __float2bfloat16(v.x), h1 = __float2bfloat16(v.y);
    __nv_bfloat16 h2 = __float2bfloat16(v.z), h3 = __float2bfloat16(v.w);
    __nv_bfloat16 l0 = __float2bfloat16(v.x - __bfloat162float(h0));
    __nv_bfloat16 l1 = __float2bfloat16(v.y - __bfloat162float(h1));
    __nv_bfloat16 l2 = __float2bfloat16(v.z - __bfloat162float(h2));
    __nv_bfloat16 l3 = __float2bfloat16(v.w - __bfloat162float(h3));
    __nv_bfloat162* H = reinterpret_cast<__nv_bfloat162*>(hi);
    __nv_bfloat162* L = reinterpret_cast<__nv_bfloat162*>(lo);
    __nv_bfloat162 p;
    p.x = h0; p.y = h1; H[2 * i] = p;
    p.x = h2; p.y = h3; H[2 * i + 1] = p;
    p.x = l0; p.y = l1; L[2 * i] = p;
    p.x = l2; p.y = l3; L[2 * i + 1] = p;
}

__global__ void convW4(const float* __restrict__ W0, const float* __restrict__ W1,
                       const float* __restrict__ W2, const float* __restrict__ W3,
                       __nv_bfloat16* __restrict__ Th,
                       __nv_bfloat16* __restrict__ Tl)
{
    __shared__ float t[32][33];
    int z = blockIdx.z;
    const float* W = (z == 0) ? W0 : (z == 1) ? W1 : (z == 2) ? W2 : W3;
    float scale = (z == 0) ? 0.125f : 1.0f;
    int row_off = z << 10;
    int n0 = blockIdx.x * 32, k0 = blockIdx.y * 32;
    int tr = threadIdx.x >> 5, tc = threadIdx.x & 31;
#pragma unroll
    for (int i = 0; i < 4; i++)
        t[tr + i * 8][tc] = W[(size_t)(k0 + tr + i * 8) * 1024 + n0 + tc];
    __syncthreads();
#pragma unroll
    for (int i = 0; i < 4; i++) {
        float x = t[tc][tr + i * 8] * scale;
        __nv_bfloat16 h = __float2bfloat16(x);
        __nv_bfloat16 l = __float2bfloat16(x - __bfloat162float(h));
        size_t o = (size_t)(row_off + n0 + tr + i * 8) * 1024 + k0 + tc;
        Th[o] = h;
        Tl[o] = l;
    }
}

__global__ void pack_bias(const float* __restrict__ bq, const float* __restrict__ bk,
                          const float* __restrict__ bv, float* __restrict__ out)
{
    int i = blockIdx.x * blockDim.x + threadIdx.x;
    if (i < 1024) out[i] = bq[i] * 0.125f;        // fold HEAD_DIM^-0.5 into q
    else if (i < 2048) out[i] = bk[i - 1024];
    else if (i < 3072) out[i] = bv[i - 2048];
}

// ---------------------------------------------------------------------------
// Axial RoPE on one (even,odd) column pair (GEMM epilogue).
// ---------------------------------------------------------------------------
__device__ __forceinline__ void rope2(float2& v, int mr, int nc)
{
    if (nc >= 2048) return;                  // v: no rope
    int hc = nc & 63;
    if (hc >= 60) return;                    // un-rotated tail
    int seg = hc / 20;
    int wp = (hc % 20) >> 1;                 // pair index 0..9
    int s = mr & (SQ - 1);
    int pos = (seg == 0) ? (s >> 8) : ((seg == 1) ? ((s >> 4) & 15) : (s & 15));
    int i0 = (2 * wp) % 10, i1 = (2 * wp + 1) % 10;
    float fp = (float)pos;
    float th0 = fp * powf(1e4f, -0.1f * (float)i0);
    float th1 = fp * powf(1e4f, -0.1f * (float)i1);
    float sn0, cs0, sn1, cs1;
    sincosf(th0, &sn0, &cs0);
    sincosf(th1, &sn1, &cs1);
    float r0 = v.x * cs0 - v.y * sn0;
    float r1 = v.y * cs1 + v.x * sn1;
    v.x = r0; v.y = r1;
}

__device__ __forceinline__ __nv_bfloat162 split_hi(float2 v, __nv_bfloat162& lo)
{
    __nv_bfloat16 h0 = __float2bfloat16(v.x), h1 = __float2bfloat16(v.y);
    lo.x = __float2bfloat16(v.x - __bfloat162float(h0));
    lo.y = __float2bfloat16(v.y - __bfloat162float(h1));
    __nv_bfloat162 hi; hi.x = h0; hi.y = h1;
    return hi;
}

// ---------------------------------------------------------------------------
// bf16x3 GEMM, 128x128 tile, 2 CTAs/SM, cp.async double-buffered.
// Stage = Ahi|Alo(10240 each) | Bhi|Blo(10240 each) = 40960 B; x2 = 80KB/CTA.
// 8 warps: 4(m) x 2(n); warp tile 32x64. B fragments staged in half-pairs
// to stay under the 128-register cap.
// ---------------------------------------------------------------------------
#define ROWB 80
#define GSTG 40960
#define GSMEM (2 * GSTG)

__device__ __forceinline__ void gemm_stage(char* dst, const __nv_bfloat16* Ah,
    const __nv_bfloat16* Al, const __nv_bfloat16* Bh, const __nv_bfloat16* Bl,
    int m0, int n0, int kc, int tid)
{
    uint32_t db = smem_u32(dst);
#pragma unroll
    for (int i = 0; i < 2; i++) {
        int e = tid + i * 256;              // 0..511
        int r = e >> 2, q = e & 3;
        size_t ga = (size_t)(m0 + r) * 1024 + kc * 32 + q * 8;
        size_t gb = (size_t)(n0 + r) * 1024 + kc * 32 + q * 8;
        uint32_t so = (uint32_t)(r * ROWB + q * 16);
        cpasync16(db + so,         Ah + ga);
        cpasync16(db + 10240 + so, Al + ga);
        cpasync16(db + 20480 + so, Bh + gb);
        cpasync16(db + 30720 + so, Bl + gb);
    }
    cpcommit();
}

template <int ROPE>
__global__ void __launch_bounds__(256, 2)
gemm_mma(const __nv_bfloat16* __restrict__ Ah, const __nv_bfloat16* __restrict__ Al,
         const __nv_bfloat16* __restrict__ Bh, const __nv_bfloat16* __restrict__ Bl,
         const float* __restrict__ bias, float* __restrict__ Cf,
         __nv_bfloat16* __restrict__ Ch, __nv_bfloat16* __restrict__ Cl, int Ntot)
{
    extern __shared__ __align__(16) char sm[];

    const int tid = threadIdx.x;
    const int l = tid & 31;
    const int w = tid >> 5;
    const int wm = w & 3;            // 4 m-warps x 32 rows
    const int wn = w >> 2;           // 2 n-warps x 64 cols
    const int m0 = blockIdx.y * 128;
    const int n0 = blockIdx.x * 128;
    const uint32_t sb = smem_u32(sm);

    float acc[2][8][4];
#pragma unroll
    for (int mt = 0; mt < 2; mt++)
#pragma unroll
        for (int nj = 0; nj < 8; nj++)
#pragma unroll
            for (int c = 0; c < 4; c++) acc[mt][nj][c] = 0.0f;

    const int a_row = wm * 32 + (l & 15);
    const int a_kb  = (l & 16);
    const int b_rbase = wn * 64 + (l & 7) + ((l & 16) >> 1);
    const int b_kb  = ((l & 8) << 1);

    gemm_stage(sm, Ah, Al, Bh, Bl, m0, n0, 0, tid);

    for (int kc = 0; kc < 32; kc++) {
        int buf = kc & 1;
        cpwait0();
        __syncthreads();
        if (kc + 1 < 32)
            gemm_stage(sm + (buf ^ 1) * GSTG, Ah, Al, Bh, Bl,
                       m0, n0, kc + 1, tid);

        const uint32_t sA = sb + buf * GSTG;
        const uint32_t sB = sA + 20480;
#pragma unroll
        for (int ks = 0; ks < 2; ks++) {
            const int kk = ks * 32;
            uint32_t ah[2][4], al[2][4];
#pragma unroll
            for (int mt = 0; mt < 2; mt++) {
                uint32_t ad = sA + (a_row + mt * 16) * ROWB + kk + a_kb;
                ldsm4(ah[mt], ad);
                ldsm4(al[mt], ad + 10240);
            }
            // B fragments in half-pairs (np = 2*hf + {0,1}) to cap registers
#pragma unroll
            for (int hf = 0; hf < 2; hf++) {
                uint32_t bh[2][4], bl[2][4];
#pragma unroll
                for (int g = 0; g < 2; g++) {
                    uint32_t bd = sB + (b_rbase + (2 * hf + g) * 16) * ROWB + kk + b_kb;
                    ldsm4(bh[g], bd);
                    ldsm4(bl[g], bd + 10240);
                }
                // pass 0: Ah*Bl — 8 distinct accumulators before reuse
#pragma unroll
                for (int mt = 0; mt < 2; mt++)
#pragma unroll
                    for (int g = 0; g < 2; g++) {
                        int np = 2 * hf + g;
                        mma16816(acc[mt][2 * np],     ah[mt], &bl[g][0]);
                        mma16816(acc[mt][2 * np + 1], ah[mt], &bl[g][2]);
                    }
                // pass 1: Al*Bh
#pragma unroll
                for (int mt = 0; mt < 2; mt++)
#pragma unroll
                    for (int g = 0; g < 2; g++) {
                        int np = 2 * hf + g;
                        mma16816(acc[mt][2 * np],     al[mt], &bh[g][0]);
                        mma16816(acc[mt][2 * np + 1], al[mt], &bh[g][2]);
                    }
                // pass 2: Ah*Bh
#pragma unroll
                for (int mt = 0; mt < 2; mt++)
#pragma unroll
                    for (int g = 0; g < 2; g++) {
                        int np = 2 * hf + g;
                        mma16816(acc[mt][2 * np],     ah[mt], &bh[g][0]);
                        mma16816(acc[mt][2 * np + 1], ah[mt], &bh[g][2]);
                    }
            }
        }
        __syncthreads();   // all warps done reading buf before it is re-staged
    }

    const int mbase = m0 + wm * 32 + (l >> 2);
    const int nbase = n0 + wn * 64 + 2 * (l & 3);
#pragma unroll
    for (int mt = 0; mt < 2; mt++)
#pragma unroll
        for (int nj = 0; nj < 8; nj++) {
            int mr = mbase + mt * 16;
            int nc = nbase + nj * 8;
            float b0 = bias[nc], b1 = bias[nc + 1];
            float2 v0 = make_float2(acc[mt][nj][0] + b0, acc[mt][nj][1] + b1);
            float2 v1 = make_float2(acc[mt][nj][2] + b0, acc[mt][nj][3] + b1);
            if (ROPE) {
                rope2(v0, mr, nc);
                rope2(v1, mr + 8, nc);
                __nv_bfloat162 lo0, lo1;
                __nv_bfloat162 hi0 = split_hi(v0, lo0);
                __nv_bfloat162 hi1 = split_hi(v1, lo1);
                *reinterpret_cast<__nv_bfloat162*>(&Ch[(size_t)mr * Ntot + nc]) = hi0;
                *reinterpret_cast<__nv_bfloat162*>(&Cl[(size_t)mr * Ntot + nc]) = lo0;
                *reinterpret_cast<__nv_bfloat162*>(&Ch[(size_t)(mr + 8) * Ntot + nc]) = hi1;
                *reinterpret_cast<__nv_bfloat162*>(&Cl[(size_t)(mr + 8) * Ntot + nc]) = lo1;
            } else {
                *reinterpret_cast<float2*>(&Cf[(size_t)mr * Ntot + nc]) = v0;
                *reinterpret_cast<float2*>(&Cf[(size_t)(mr + 8) * Ntot + nc]) = v1;
            }
        }
}

// ---------------------------------------------------------------------------
// Flash attention (unchanged from R14): mma.sync bf16x3, exact fp32 online
// softmax, cp.async double-buffered K/V, 2 CTAs/SM.
// ---------------------------------------------------------------------------
#define FROW 144
#define KVSTG 36864
#define sPh 73728
#define sPl 92160
#define FSMEM 110592

__device__ __forceinline__ void kv_stage(char* smbase, int stg,
    const __nv_bfloat16* qkvh, const __nv_bfloat16* qkvl,
    int b, int h, int kt, int tid)
{
    uint32_t db = smem_u32(smbase) + stg * KVSTG;
#pragma unroll
    for (int i = 0; i < 8; i++) {
        int e = tid + i * 256;
        int buf = e >> 9, r = (e >> 3) & 63, c8 = e & 7;
        const __nv_bfloat16* sp = (buf & 1) ? qkvl : qkvh;
        int coloff = ((buf < 2) ? 1024 : 2048) + h * 64;
        size_t g = (size_t)(b * SQ + kt * 64 + r) * 3072 + coloff + c8 * 8;
        cpasync16(db + buf * 9216 + r * FROW + c8 * 16, sp + g);
    }
    cpcommit();
}

__global__ void __launch_bounds__(256, 2)
flash_mma(const __nv_bfloat16* __restrict__ qkvh,
          const __nv_bfloat16* __restrict__ qkvl,
          __nv_bfloat16* __restrict__ ctxh,
          __nv_bfloat16* __restrict__ ctxl)
{
    extern __shared__ __align__(16) char fsm[];
    const int tid = threadIdx.x, l = tid & 31, w = tid >> 5;
    const int bh = blockIdx.y, b = bh >> 4, h = bh & 15;
    const int q0 = blockIdx.x * 128;
    const uint32_t sb = smem_u32(fsm);

    // ---- stage Q hi/lo via the P area, load Q fragments to registers ----
#pragma unroll
    for (int i = 0; i < 8; i++) {
        int e = tid + i * 256;
        int buf = e >> 10, r = (e >> 3) & 127, c8 = e & 7;
        const __nv_bfloat16* sp = buf ? qkvl : qkvh;
        size_t g = (size_t)(b * SQ + q0 + r) * 3072 + h * 64 + c8 * 8;
        *reinterpret_cast<float4*>(fsm + (buf ? sPl : sPh) + r * FROW + c8 * 16) =
            *reinterpret_cast<const float4*>(sp + g);
    }
    __syncthreads();

    uint32_t qh[4][4], ql[4][4];
    {
        uint32_t aQ = sb + sPh + (w * 16 + (l & 15)) * FROW + (l >> 4) * 16;
#pragma unroll
        for (int ks = 0; ks < 4; ks++) {
            ldsm4(qh[ks], aQ + ks * 32);
            ldsm4(ql[ks], aQ + ks * 32 + (sPl - sPh));
        }
    }

    // prefetch first K/V tile
    kv_stage(fsm, 0, qkvh, qkvl, b, h, 0, tid);

    float o[8][4];
    float mrow[2] = { -1e30f, -1e30f };
    float lsum[2] = { 0.0f, 0.0f };
#pragma unroll
    for (int nj = 0; nj < 8; nj++)
#pragma unroll
        for (int c = 0; c < 4; c++) o[nj][c] = 0.0f;

    for (int kt = 0; kt < SQ / 64; kt++) {
        int stg = kt & 1;
        cpwait0();
        __syncthreads();   // K/V(kt) ready; all threads done with buf stg^1
        if (kt + 1 < SQ / 64)
            kv_stage(fsm, stg ^ 1, qkvh, qkvl, b, h, kt + 1, tid);

        const uint32_t sK = sb + stg * KVSTG;
        const uint32_t sV = sK + 18432;

        // ---- MMA1: S = Q @ K^T (bf16x3), half-pair fragment staging ----
        float sacc[8][4];
#pragma unroll
        for (int nj = 0; nj < 8; nj++)
#pragma unroll
            for (int c = 0; c < 4; c++) sacc[nj][c] = 0.0f;

        uint32_t aK = sK + ((l & 7) + ((l & 16) >> 1)) * FROW + ((l & 8) << 1);
#pragma unroll
        for (int ks = 0; ks < 4; ks++)
#pragma unroll
            for (int hf = 0; hf < 2; hf++) {
                uint32_t bkh[2][4], bkl[2][4];
#pragma unroll
                for (int g = 0; g < 2; g++) {
                    uint32_t ad = aK + (2 * hf + g) * (16 * FROW) + ks * 32;
                    ldsm4(bkh[g], ad);
                    ldsm4(bkl[g], ad + 9216);
                }
#pragma unroll
                for (int g = 0; g < 2; g++) {
                    int ng = 2 * hf + g;
                    mma16816(sacc[2 * ng],     qh[ks], &bkl[g][0]);
                    mma16816(sacc[2 * ng + 1], qh[ks], &bkl[g][2]);
                }
#pragma unroll
                for (int g = 0; g < 2; g++) {
                    int ng = 2 * hf + g;
                    mma16816(sacc[2 * ng],     ql[ks], &bkh[g][0]);
                    mma16816(sacc[2 * ng + 1], ql[ks], &bkh[g][2]);
                }
#pragma unroll
                for (int g = 0; g < 2; g++) {
                    int ng = 2 * hf + g;
                    mma16816(sacc[2 * ng],     qh[ks], &bkh[g][0]);
                    mma16816(sacc[2 * ng + 1], qh[ks], &bkh[g][2]);
                }
            }

        // ---- online softmax ----
#pragma unroll
        for (int rr = 0; rr < 2; rr++) {
            float vm = -1e30f;
#pragma unroll
            for (int nj = 0; nj < 8; nj++)
                vm = fmaxf(vm, fmaxf(sacc[nj][2 * rr], sacc[nj][2 * rr + 1]));
            vm = fmaxf(vm, __shfl_xor_sync(0xffffffffu, vm, 1));
            vm = fmaxf(vm, __shfl_xor_sync(0xffffffffu, vm, 2));
            float mn = fmaxf(mrow[rr], vm);
            float alpha = __expf(mrow[rr] - mn);
            mrow[rr] = mn;
            float rs = 0.0f;
#pragma unroll
            for (int nj = 0; nj < 8; nj++) {
                float p0 = __expf(sacc[nj][2 * rr] - mn);
                float p1 = __expf(sacc[nj][2 * rr + 1] - mn);
                sacc[nj][2 * rr] = p0;
                sacc[nj][2 * rr + 1] = p1;
                rs += p0 + p1;
            }
            rs += __shfl_xor_sync(0xffffffffu, rs, 1);
            rs += __shfl_xor_sync(0xffffffffu, rs, 2);
            lsum[rr] = lsum[rr] * alpha + rs;
#pragma unroll
            for (int nj = 0; nj < 8; nj++) {
                o[nj][2 * rr] *= alpha;
                o[nj][2 * rr + 1] *= alpha;
            }
            int prow = w * 16 + (l >> 2) + rr * 8;
#pragma unroll
            for (int nj = 0; nj < 8; nj++) {
                float2 pv = make_float2(sacc[nj][2 * rr], sacc[nj][2 * rr + 1]);
                __nv_bfloat162 plo;
                __nv_bfloat162 phi = split_hi(pv, plo);
                int cb = (nj * 8 + 2 * (l & 3)) * 2;
                *reinterpret_cast<__nv_bfloat162*>(fsm + sPh + prow * FROW + cb) = phi;
                *reinterpret_cast<__nv_bfloat162*>(fsm + sPl + prow * FROW + cb) = plo;
            }
        }
        __syncwarp();   // P rows are warp-private

        // ---- MMA2: O += P @ V (bf16x3, half-pair staging) ----
        uint32_t aP = sb + sPh + (w * 16 + (l & 15)) * FROW + (l >> 4) * 16;
        uint32_t aV = sV + (l & 15) * FROW + (l >> 4) * 16;
#pragma unroll
        for (int ks = 0; ks < 4; ks++) {
            uint32_t ph[4], pl[4];
            ldsm4(ph, aP + ks * 32);
            ldsm4(pl, aP + ks * 32 + (sPl - sPh));
#pragma unroll
            for (int hf = 0; hf < 2; hf++) {
                uint32_t bvh[2][4], bvl[2][4];
#pragma unroll
                for (int g = 0; g < 2; g++) {
                    uint32_t ad = aV + ks * (16 * FROW) + (2 * hf + g) * 32;
                    ldsm4t(bvh[g], ad);
                    ldsm4t(bvl[g], ad + 9216);
                }
#pragma unroll
                for (int g = 0; g < 2; g++) {
                    int ng = 2 * hf + g;
                    mma16816(o[2 * ng],     ph, &bvl[g][0]);
                    mma16816(o[2 * ng + 1], ph, &bvl[g][2]);
                }
#pragma unroll
                for (int g = 0; g < 2; g++) {
                    int ng = 2 * hf + g;
                    mma16816(o[2 * ng],     pl, &bvh[g][0]);
                    mma16816(o[2 * ng + 1], pl, &bvh[g][2]);
                }
#pragma unroll
                for (int g = 0; g < 2; g++) {
                    int ng = 2 * hf + g;
                    mma16816(o[2 * ng],     ph, &bvh[g][0]);
                    mma16816(o[2 * ng + 1], ph, &bvh[g][2]);
                }
            }
        }
    }

    // ---- epilogue ----
#pragma unroll
    for (int rr = 0; rr < 2; rr++) {
        float inv = 1.0f / lsum[rr];
        size_t row = (size_t)(b * SQ + q0 + w * 16 + (l >> 2) + rr * 8);
#pragma unroll
        for (int nj = 0; nj < 8; nj++) {
            float2 cv = make_float2(o[nj][2 * rr] * inv, o[nj][2 * rr + 1] * inv);
            int col = h * 64 + nj * 8 + 2 * (l & 3);
            __nv_bfloat162 lo;
            __nv_bfloat162 hi = split_hi(cv, lo);
            *reinterpret_cast<__nv_bfloat162*>(&ctxh[row * HID + col]) = hi;
            *reinterpret_cast<__nv_bfloat162*>(&ctxl[row * HID + col]) = lo;
        }
    }
}

// ---------------------------------------------------------------------------
extern "C" void kernel_launch(void* const* d_in, const int* in_sizes, int n_in,
                              void* d_out, int out_size)
{
    (void)in_sizes; (void)n_in; (void)out_size;
    const float* hs = (const float*)d_in[0];
    const float* Wq = (const float*)d_in[1];
    const float* bq = (const float*)d_in[2];
    const float* Wk = (const float*)d_in[3];
    const float* bk = (const float*)d_in[4];
    const float* Wv = (const float*)d_in[5];
    const float* bv = (const float*)d_in[6];
    const float* Wo = (const float*)d_in[7];
    const float* bo = (const float*)d_in[8];

    __nv_bfloat16 *ahi, *alo, *wthi, *wtlo, *qkvh, *qkvl;
    float* bias;
    cudaGetSymbolAddress((void**)&ahi, g_ahi);
    cudaGetSymbolAddress((void**)&alo, g_alo);
    cudaGetSymbolAddress((void**)&wthi, g_wthi);
    cudaGetSymbolAddress((void**)&wtlo, g_wtlo);
    cudaGetSymbolAddress((void**)&bias, g_bias);
    cudaGetSymbolAddress((void**)&qkvh, g_qkvh);
    cudaGetSymbolAddress((void**)&qkvl, g_qkvl);

    cudaFuncSetAttribute(gemm_mma<1>,
                         cudaFuncAttributeMaxDynamicSharedMemorySize, GSMEM);
    cudaFuncSetAttribute(gemm_mma<0>,
                         cudaFuncAttributeMaxDynamicSharedMemorySize, GSMEM);
    cudaFuncSetAttribute(flash_mma,
                         cudaFuncAttributeMaxDynamicSharedMemorySize, FSMEM);

    // conversions (Wq/bq pre-scaled by HEAD_DIM^-0.5 = 0.125)
    convert_hilo<<<(MROWS * HID / 4 + 255) / 256, 256>>>(hs, ahi, alo, MROWS * HID / 4);
    convW4<<<dim3(32, 32, 4), 256>>>(Wq, Wk, Wv, Wo, wthi, wtlo);
    pack_bias<<<12, 256>>>(bq, bk, bv, bias);

    // fused QKV projection with rope + hi/lo split in epilogue
    gemm_mma<1><<<dim3(24, 32), 256, GSMEM>>>(
        ahi, alo, wthi, wtlo, bias, nullptr, qkvh, qkvl, 3072);

    // flash attention -> ctx hi/lo (reuses g_ahi/g_alo)
    flash_mma<<<dim3(SQ / 128, BQ * NH), 256, FSMEM>>>(qkvh, qkvl, ahi, alo);

    // O projection -> fp32 output
    gemm_mma<0><<<dim3(8, 32), 256, GSMEM>>>(
        ahi, alo, wthi + (size_t)3072 * 1024, wtlo + (size_t)3072 * 1024,
        bo, (float*)d_out, nullptr, nullptr, 1024);
}